// round 1
// baseline (speedup 1.0000x reference)
#include <cuda_runtime.h>
#include <cuda_bf16.h>

#define BB 2
#define CC 256
#define HH 48
#define WW 48
#define HWP 2304        // H*W pixels
#define DM 256          // d_model
#define NH 8
#define DK 32
#define QK_SCALE 0.17677669529663689f   // 1/sqrt(32)

// Scratch (allocation-free): Q,K,V,O as (B, HW, d_model), d contiguous.
__device__ float g_Q[BB * HWP * DM];
__device__ float g_K[BB * HWP * DM];
__device__ float g_V[BB * HWP * DM];
__device__ float g_O[BB * HWP * DM];

// ---------------------------------------------------------------------------
// Kernel 1: fused QKV projection + positional encoding + bias.
// Per block: 64 pixels x 64 dims for Q, K, V (shared x tile).
// Thread mapping: p(i) = (tid>>4)*4 + i   (4 consecutive pixels)
//                 d(j) = (tid&15) + 16*j  (4 strided dims -> coalesced stores)
// ---------------------------------------------------------------------------
__global__ __launch_bounds__(256) void qkv_kernel(
    const float* __restrict__ x,
    const float* __restrict__ Wq, const float* __restrict__ bq,
    const float* __restrict__ Wk, const float* __restrict__ bk,
    const float* __restrict__ Wv, const float* __restrict__ bv)
{
    __shared__ float xs[32][64];
    __shared__ float wqs[64][33];
    __shared__ float wks[64][33];
    __shared__ float wvs[64][33];

    const int b     = blockIdx.z;
    const int pBase = blockIdx.x * 64;
    const int dBase = blockIdx.y * 64;
    const int tid   = threadIdx.x;

    const int pg = (tid >> 4) * 4;   // pixel group base (0..60)
    const int dg = (tid & 15);       // dim lane (0..15), dims dg+16j

    float aq[4][4] = {};
    float ak[4][4] = {};
    float av[4][4] = {};

    for (int c0 = 0; c0 < CC; c0 += 32) {
        // x tile: 32 c x 64 p, coalesced along p
        #pragma unroll
        for (int i = tid; i < 32 * 64; i += 256) {
            int kk = i >> 6, pp = i & 63;
            xs[kk][pp] = x[(size_t)b * CC * HWP + (size_t)(c0 + kk) * HWP + pBase + pp];
        }
        // weight tiles: 64 d x 32 c, coalesced along c
        #pragma unroll
        for (int i = tid; i < 64 * 32; i += 256) {
            int dd = i >> 5, kk = i & 31;
            int widx = (dBase + dd) * CC + c0 + kk;
            wqs[dd][kk] = Wq[widx];
            wks[dd][kk] = Wk[widx];
            wvs[dd][kk] = Wv[widx];
        }
        __syncthreads();

        #pragma unroll
        for (int kk = 0; kk < 32; kk++) {
            float a[4];
            #pragma unroll
            for (int i = 0; i < 4; i++) a[i] = xs[kk][pg + i];
            #pragma unroll
            for (int j = 0; j < 4; j++) {
                int drow = dg + 16 * j;
                float wqv = wqs[drow][kk];
                float wkv = wks[drow][kk];
                float wvv = wvs[drow][kk];
                #pragma unroll
                for (int i = 0; i < 4; i++) {
                    aq[i][j] += a[i] * wqv;
                    ak[i][j] += a[i] * wkv;
                    av[i][j] += a[i] * wvv;
                }
            }
        }
        __syncthreads();
    }

    // Epilogue: + bias + positional encoding (Q,K only), write to scratch.
    #pragma unroll
    for (int j = 0; j < 4; j++) {
        const int d = dBase + dg + 16 * j;
        const float bqv = bq[d], bkv = bk[d], bvv = bv[d];
        const int dl   = (d < 128) ? d : (d - 128);
        const int i2   = dl >> 1;
        // div[i] = exp(-i * ln(10000)/64)
        const float freq   = __expf(-(float)i2 * 0.14391156642875743f);
        const bool  use_y  = (d >= 128);
        const bool  is_cos = (dl & 1);
        #pragma unroll
        for (int i = 0; i < 4; i++) {
            const int p = pBase + pg + i;
            const float coord = use_y ? (float)(p / WW) : (float)(p % WW);
            const float arg = coord * freq;
            const float pe = is_cos ? __cosf(arg) : __sinf(arg);
            const size_t idx = ((size_t)b * HWP + p) * DM + d;
            g_Q[idx] = aq[i][j] + bqv + pe;
            g_K[idx] = ak[i][j] + bkv + pe;
            g_V[idx] = av[i][j] + bvv;
        }
    }
}

// ---------------------------------------------------------------------------
// Kernel 2: flash-style attention per (b, head), fp32 SIMT.
// Block = 128 threads, 64 query rows; loop over 36 key tiles of 64.
// Distance-prior bias via shared 48x48 bf16 table (exp(-sqrt(dy^2+dx^2))).
// ---------------------------------------------------------------------------
__global__ __launch_bounds__(128) void attn_kernel(const float* __restrict__ lambda_p)
{
    __shared__ float Qs[64][33];
    __shared__ float Ks[64][33];
    __shared__ float Vs[64][33];
    __shared__ float Ss[64][65];
    __shared__ __nv_bfloat16 dmt[HH * WW];
    __shared__ float mrow[64], lrow[64], alphas[64];

    const int bh      = blockIdx.z;
    const int b       = bh >> 3;
    const int h       = bh & 7;
    const int rowBase = blockIdx.y * 64;
    const int tid     = threadIdx.x;
    const float lam   = *lambda_p;

    // distance table: dm(dy,dx) = exp(-sqrt(dy^2+dx^2)) (sigma = 1)
    for (int i = tid; i < HH * WW; i += 128) {
        int dy = i / WW, dx = i % WW;
        dmt[i] = __float2bfloat16(__expf(-sqrtf((float)(dy * dy + dx * dx))));
    }
    // Q tile (64 x 32), coalesced along k
    for (int i = tid; i < 64 * 32; i += 128) {
        int r = i >> 5, k = i & 31;
        Qs[r][k] = g_Q[((size_t)b * HWP + rowBase + r) * DM + h * DK + k];
    }
    if (tid < 64) { mrow[tid] = -1e30f; lrow[tid] = 0.0f; }

    // S phase mapping: rows sr0+i, cols sc + 8*j (interleaved -> conflict-free Ks reads)
    const int sr0 = (tid >> 3) * 4;
    const int sc  = (tid & 7);
    // PV phase mapping: rows pr0+i, dims pd0+jd
    const int pr0 = (tid >> 3) * 4;
    const int pd0 = (tid & 7) * 4;

    float acc[4][4] = {};
    __syncthreads();

    for (int jt = 0; jt < HWP; jt += 64) {
        // K,V tiles
        for (int i = tid; i < 64 * 32; i += 128) {
            int r = i >> 5, k = i & 31;
            size_t gi = ((size_t)b * HWP + jt + r) * DM + h * DK + k;
            Ks[r][k] = g_K[gi];
            Vs[r][k] = g_V[gi];
        }
        __syncthreads();

        // S = (Q K^T) * scale
        {
            float s[4][8] = {};
            #pragma unroll
            for (int k = 0; k < 32; k++) {
                float a[4], bb[8];
                #pragma unroll
                for (int i = 0; i < 4; i++) a[i] = Qs[sr0 + i][k];
                #pragma unroll
                for (int j = 0; j < 8; j++) bb[j] = Ks[sc + 8 * j][k];
                #pragma unroll
                for (int i = 0; i < 4; i++)
                    #pragma unroll
                    for (int j = 0; j < 8; j++)
                        s[i][j] += a[i] * bb[j];
            }
            #pragma unroll
            for (int i = 0; i < 4; i++)
                #pragma unroll
                for (int j = 0; j < 8; j++)
                    Ss[sr0 + i][sc + 8 * j] = s[i][j] * QK_SCALE;
        }
        __syncthreads();

        // Online softmax: one thread per row (tid < 64), conflict-free row scans.
        if (tid < 64) {
            const int r  = tid;
            const int ig = rowBase + r;
            const int yi = ig / WW, xi = ig % WW;
            const float m_old = mrow[r];
            float tmax = -1e30f;
            #pragma unroll 4
            for (int j = 0; j < 64; j++) {
                const int jg = jt + j;
                const int yj = jg / WW, xj = jg % WW;
                int dy = yi - yj; dy = (dy < 0) ? -dy : dy;
                int dx = xi - xj; dx = (dx < 0) ? -dx : dx;
                float sv = Ss[r][j] + lam * __bfloat162float(dmt[dy * WW + dx]);
                Ss[r][j] = sv;
                tmax = fmaxf(tmax, sv);
            }
            const float m_new = fmaxf(m_old, tmax);
            const float alpha = __expf(m_old - m_new);
            float lsum = 0.0f;
            #pragma unroll 4
            for (int j = 0; j < 64; j++) {
                float p = __expf(Ss[r][j] - m_new);
                Ss[r][j] = p;
                lsum += p;
            }
            mrow[r]   = m_new;
            alphas[r] = alpha;
            lrow[r]   = lrow[r] * alpha + lsum;
        }
        __syncthreads();

        // Rescale accumulators and accumulate P @ V
        {
            float al[4];
            #pragma unroll
            for (int i = 0; i < 4; i++) al[i] = alphas[pr0 + i];
            #pragma unroll
            for (int i = 0; i < 4; i++)
                #pragma unroll
                for (int jd = 0; jd < 4; jd++)
                    acc[i][jd] *= al[i];

            #pragma unroll 8
            for (int j = 0; j < 64; j++) {
                float pv[4], vv[4];
                #pragma unroll
                for (int i = 0; i < 4; i++) pv[i] = Ss[pr0 + i][j];
                #pragma unroll
                for (int jd = 0; jd < 4; jd++) vv[jd] = Vs[j][pd0 + jd];
                #pragma unroll
                for (int i = 0; i < 4; i++)
                    #pragma unroll
                    for (int jd = 0; jd < 4; jd++)
                        acc[i][jd] += pv[i] * vv[jd];
            }
        }
        __syncthreads();
    }

    // Normalize and write O
    #pragma unroll
    for (int i = 0; i < 4; i++) {
        const float inv = 1.0f / lrow[pr0 + i];
        const int p = rowBase + pr0 + i;
        #pragma unroll
        for (int jd = 0; jd < 4; jd++)
            g_O[((size_t)b * HWP + p) * DM + h * DK + pd0 + jd] = acc[i][jd] * inv;
    }
}

// ---------------------------------------------------------------------------
// Kernel 3: output projection + residual:  y = x + bo + gamma * (Wo @ O)
// Output layout (B, C, HW); p varies fastest across lanes -> coalesced.
// ---------------------------------------------------------------------------
__global__ __launch_bounds__(256) void outproj_kernel(
    const float* __restrict__ x, const float* __restrict__ Wo,
    const float* __restrict__ bo, const float* __restrict__ gamma_p,
    float* __restrict__ out)
{
    __shared__ float Os[64][33];
    __shared__ float Wos[64][33];

    const int b     = blockIdx.z;
    const int pBase = blockIdx.x * 64;
    const int cBase = blockIdx.y * 64;
    const int tid   = threadIdx.x;

    const int pl = (tid & 15);        // pixels pl + 16*i
    const int cg = (tid >> 4) * 4;    // channels cg + j
    const float gamma = *gamma_p;

    float acc[4][4] = {};

    for (int k0 = 0; k0 < DM; k0 += 32) {
        #pragma unroll
        for (int i = tid; i < 64 * 32; i += 256) {
            int r = i >> 5, k = i & 31;
            Os[r][k]  = g_O[((size_t)b * HWP + pBase + r) * DM + k0 + k];
            Wos[r][k] = Wo[(cBase + r) * DM + k0 + k];
        }
        __syncthreads();

        #pragma unroll
        for (int k = 0; k < 32; k++) {
            float a[4], w[4];
            #pragma unroll
            for (int i = 0; i < 4; i++) a[i] = Os[pl + 16 * i][k];
            #pragma unroll
            for (int j = 0; j < 4; j++) w[j] = Wos[cg + j][k];
            #pragma unroll
            for (int i = 0; i < 4; i++)
                #pragma unroll
                for (int j = 0; j < 4; j++)
                    acc[i][j] += a[i] * w[j];
        }
        __syncthreads();
    }

    #pragma unroll
    for (int j = 0; j < 4; j++) {
        const int c = cBase + cg + j;
        const float bias = bo[c];
        #pragma unroll
        for (int i = 0; i < 4; i++) {
            const int p = pBase + pl + 16 * i;
            const size_t idx = (size_t)b * CC * HWP + (size_t)c * HWP + p;
            out[idx] = x[idx] + gamma * acc[i][j] + bias;
        }
    }
}

// ---------------------------------------------------------------------------
extern "C" void kernel_launch(void* const* d_in, const int* in_sizes, int n_in,
                              void* d_out, int out_size)
{
    (void)in_sizes; (void)n_in; (void)out_size;
    const float* x   = (const float*)d_in[0];
    const float* Wq  = (const float*)d_in[1];
    const float* bq  = (const float*)d_in[2];
    const float* Wk  = (const float*)d_in[3];
    const float* bk  = (const float*)d_in[4];
    const float* Wv  = (const float*)d_in[5];
    const float* bv  = (const float*)d_in[6];
    const float* Wo  = (const float*)d_in[7];
    const float* bo  = (const float*)d_in[8];
    const float* lam = (const float*)d_in[9];
    const float* gam = (const float*)d_in[10];
    float* out = (float*)d_out;

    dim3 g1(HWP / 64, DM / 64, BB);
    qkv_kernel<<<g1, 256>>>(x, Wq, bq, Wk, bk, Wv, bv);

    dim3 g2(1, HWP / 64, BB * NH);
    attn_kernel<<<g2, 128>>>(lam);

    dim3 g3(HWP / 64, CC / 64, BB);
    outproj_kernel<<<g3, 256>>>(x, Wo, bo, gam, out);
}

// round 3
// speedup vs baseline: 3.0573x; 3.0573x over previous
#include <cuda_runtime.h>
#include <cuda_bf16.h>
#include <cstdint>

#define BB 2
#define CC 256
#define HH 48
#define WW 48
#define HWP 2304
#define DM 256
#define NH 8
#define DK 32
#define QK_SCALE 0.17677669529663689f   // 1/sqrt(32)
#define QPAD 40                          // padded row length (bf16 elems) = 80B

// ---------------- scratch (allocation-free) ----------------
__device__ __nv_bfloat16 g_Qb[BB * HWP * DM];   // (b, p, d) bf16
__device__ __nv_bfloat16 g_Kb[BB * HWP * DM];   // (b, p, d) bf16
__device__ __nv_bfloat16 g_Vb[BB * HWP * DM];   // (b, p, d) bf16
__device__ float         g_O [BB * HWP * DM];   // (b, p, d) f32

// ---------------- helpers ----------------
__device__ __forceinline__ uint32_t smem_u32(const void* p) {
    uint32_t a;
    asm("{ .reg .u64 t; cvta.to.shared.u64 t, %1; cvt.u32.u64 %0, t; }" : "=r"(a) : "l"(p));
    return a;
}
__device__ __forceinline__ void ldmx4(uint32_t& r0, uint32_t& r1, uint32_t& r2, uint32_t& r3, uint32_t a) {
    asm volatile("ldmatrix.sync.aligned.m8n8.x4.shared.b16 {%0,%1,%2,%3}, [%4];"
                 : "=r"(r0), "=r"(r1), "=r"(r2), "=r"(r3) : "r"(a));
}
__device__ __forceinline__ void ldmx4t(uint32_t& r0, uint32_t& r1, uint32_t& r2, uint32_t& r3, uint32_t a) {
    asm volatile("ldmatrix.sync.aligned.m8n8.x4.trans.shared.b16 {%0,%1,%2,%3}, [%4];"
                 : "=r"(r0), "=r"(r1), "=r"(r2), "=r"(r3) : "r"(a));
}
__device__ __forceinline__ void mma16816(float* c, const uint32_t* a, const uint32_t* b) {
    asm volatile("mma.sync.aligned.m16n8k16.row.col.f32.bf16.bf16.f32 "
                 "{%0,%1,%2,%3},{%4,%5,%6,%7},{%8,%9},{%0,%1,%2,%3};"
                 : "+f"(c[0]), "+f"(c[1]), "+f"(c[2]), "+f"(c[3])
                 : "r"(a[0]), "r"(a[1]), "r"(a[2]), "r"(a[3]), "r"(b[0]), "r"(b[1]));
}

// ---------------------------------------------------------------------------
// Kernel 1: fused QKV projection + positional encoding + bias -> bf16 scratch
// ---------------------------------------------------------------------------
__global__ __launch_bounds__(256) void qkv_kernel(
    const float* __restrict__ x,
    const float* __restrict__ Wq, const float* __restrict__ bq,
    const float* __restrict__ Wk, const float* __restrict__ bk,
    const float* __restrict__ Wv, const float* __restrict__ bv)
{
    __shared__ float xs[32][64];
    __shared__ float wqs[64][33];
    __shared__ float wks[64][33];
    __shared__ float wvs[64][33];

    const int b     = blockIdx.z;
    const int pBase = blockIdx.x * 64;
    const int dBase = blockIdx.y * 64;
    const int tid   = threadIdx.x;

    const int pg = (tid >> 4) * 4;
    const int dg = (tid & 15);

    float aq[4][4] = {};
    float ak[4][4] = {};
    float av[4][4] = {};

    for (int c0 = 0; c0 < CC; c0 += 32) {
        #pragma unroll
        for (int i = tid; i < 32 * 64; i += 256) {
            int kk = i >> 6, pp = i & 63;
            xs[kk][pp] = x[(size_t)b * CC * HWP + (size_t)(c0 + kk) * HWP + pBase + pp];
        }
        #pragma unroll
        for (int i = tid; i < 64 * 32; i += 256) {
            int dd = i >> 5, kk = i & 31;
            int widx = (dBase + dd) * CC + c0 + kk;
            wqs[dd][kk] = Wq[widx];
            wks[dd][kk] = Wk[widx];
            wvs[dd][kk] = Wv[widx];
        }
        __syncthreads();

        #pragma unroll
        for (int kk = 0; kk < 32; kk++) {
            float a[4];
            #pragma unroll
            for (int i = 0; i < 4; i++) a[i] = xs[kk][pg + i];
            #pragma unroll
            for (int j = 0; j < 4; j++) {
                int drow = dg + 16 * j;
                float wqv = wqs[drow][kk];
                float wkv = wks[drow][kk];
                float wvv = wvs[drow][kk];
                #pragma unroll
                for (int i = 0; i < 4; i++) {
                    aq[i][j] += a[i] * wqv;
                    ak[i][j] += a[i] * wkv;
                    av[i][j] += a[i] * wvv;
                }
            }
        }
        __syncthreads();
    }

    #pragma unroll
    for (int j = 0; j < 4; j++) {
        const int d = dBase + dg + 16 * j;
        const float bqv = bq[d], bkv = bk[d], bvv = bv[d];
        const int dl   = (d < 128) ? d : (d - 128);
        const int i2   = dl >> 1;
        const float freq   = __expf(-(float)i2 * 0.14391156642875743f);
        const bool  use_y  = (d >= 128);
        const bool  is_cos = (dl & 1);
        #pragma unroll
        for (int i = 0; i < 4; i++) {
            const int p = pBase + pg + i;
            const float coord = use_y ? (float)(p / WW) : (float)(p % WW);
            const float arg = coord * freq;
            const float pe = is_cos ? __cosf(arg) : __sinf(arg);
            const size_t idx = ((size_t)b * HWP + p) * DM + d;
            g_Qb[idx] = __float2bfloat16(aq[i][j] + bqv + pe);
            g_Kb[idx] = __float2bfloat16(ak[i][j] + bkv + pe);
            g_Vb[idx] = __float2bfloat16(av[i][j] + bvv);
        }
    }
}

// ---------------------------------------------------------------------------
// Kernel 2: HMMA (mma.sync bf16) flash attention, no online max.
// CTA = 128 threads (4 warps), 128 query rows; 36 KV tiles of 64 keys.
// ---------------------------------------------------------------------------
__global__ __launch_bounds__(128) void attn_mma_kernel(const float* __restrict__ lambda_p)
{
    __shared__ __nv_bfloat16 Qs[128 * QPAD];
    __shared__ __nv_bfloat16 Ks[64 * QPAD];
    __shared__ __nv_bfloat16 Vs[64 * QPAD];
    __shared__ __nv_bfloat16 dmt[HH * WW];

    const int tid  = threadIdx.x;
    const int warp = tid >> 5;
    const int lane = tid & 31;
    const int b    = blockIdx.y >> 3;
    const int h    = blockIdx.y & 7;
    const int rowBase = blockIdx.x * 128;
    const float lam = *lambda_p;

    // distance table exp(-sqrt(dy^2+dx^2))
    for (int i = tid; i < HH * WW; i += 128) {
        int dy = i / WW, dx = i % WW;
        dmt[i] = __float2bfloat16(__expf(-sqrtf((float)(dy * dy + dx * dx))));
    }

    // Q tile: 128 rows x 32 dims -> padded shared rows
    {
        const __nv_bfloat16* qsrc = g_Qb + (size_t)(b * HWP + rowBase) * DM + h * DK;
        #pragma unroll
        for (int c = tid; c < 512; c += 128) {
            int r = c >> 2, q = c & 3;
            uint4 v = *(const uint4*)(qsrc + (size_t)r * DM + q * 8);
            *(uint4*)(Qs + r * QPAD + q * 8) = v;
        }
    }
    __syncthreads();

    // Q A-fragments: [mtile][kstep][4], resident
    uint32_t qa[2][2][4];
    {
        const int arow = (lane & 7) + ((lane >> 3) & 1) * 8;
        const int acol = (lane >> 4) * 8;
        #pragma unroll
        for (int m = 0; m < 2; m++)
            #pragma unroll
            for (int ks = 0; ks < 2; ks++) {
                uint32_t a = smem_u32(Qs + (warp * 32 + m * 16 + arow) * QPAD + ks * 16 + acol);
                ldmx4(qa[m][ks][0], qa[m][ks][1], qa[m][ks][2], qa[m][ks][3], a);
            }
    }

    // per-thread row coordinates (4 rows: m in {0,1}, rr in {0,1})
    int yi[2][2], xi[2][2];
    #pragma unroll
    for (int m = 0; m < 2; m++)
        #pragma unroll
        for (int rr = 0; rr < 2; rr++) {
            int g = rowBase + warp * 32 + m * 16 + (lane >> 2) + rr * 8;
            yi[m][rr] = g / WW;
            xi[m][rr] = g - yi[m][rr] * WW;
        }

    float o[2][4][4] = {};          // O accum: [m][dimtile n8][frag]
    float rsum[2][2] = {};          // row sums

    const int c2 = 2 * (lane & 3);  // fragment col base within n8

    for (int jt = 0; jt < HWP; jt += 64) {
        __syncthreads();  // previous tile's ldmatrix reads done
        // K,V tiles: 64 keys x 32 dims each
        {
            const __nv_bfloat16* kb = g_Kb + (size_t)(b * HWP + jt) * DM + h * DK;
            const __nv_bfloat16* vb = g_Vb + (size_t)(b * HWP + jt) * DM + h * DK;
            #pragma unroll
            for (int c = tid; c < 256; c += 128) {
                int r = c >> 2, q = c & 3;
                *(uint4*)(Ks + r * QPAD + q * 8) = *(const uint4*)(kb + (size_t)r * DM + q * 8);
                *(uint4*)(Vs + r * QPAD + q * 8) = *(const uint4*)(vb + (size_t)r * DM + q * 8);
            }
        }
        __syncthreads();

        // --- S = Q K^T : [m][ntile 0..7][4] ---
        float S[2][8][4] = {};
        {
            const int brow = (lane & 7) + ((lane >> 4) & 1) * 8;   // key row within n16
            const int bcol = ((lane >> 3) & 1) * 8;                // k half
            #pragma unroll
            for (int np = 0; np < 4; np++) {
                #pragma unroll
                for (int ks = 0; ks < 2; ks++) {
                    uint32_t kf[4];
                    uint32_t a = smem_u32(Ks + (np * 16 + brow) * QPAD + ks * 16 + bcol);
                    ldmx4(kf[0], kf[1], kf[2], kf[3], a);
                    #pragma unroll
                    for (int m = 0; m < 2; m++) {
                        mma16816(S[m][2 * np],     qa[m][ks], kf);
                        mma16816(S[m][2 * np + 1], qa[m][ks], kf + 2);
                    }
                }
            }
        }

        // --- P = exp(S*scale + lam*dm); pack to A-frags; accumulate row sums ---
        uint32_t pa[2][4][4];   // [m][k16 step][4]
        #pragma unroll
        for (int n = 0; n < 8; n++) {
            const int jg0 = jt + n * 8 + c2;
            const int yj0 = jg0 / WW, xj0 = jg0 - yj0 * WW;
            const int jg1 = jg0 + 1;
            const int yj1 = jg1 / WW, xj1 = jg1 - yj1 * WW;
            #pragma unroll
            for (int m = 0; m < 2; m++) {
                float p[4];
                #pragma unroll
                for (int rr = 0; rr < 2; rr++) {
                    int dy0 = yi[m][rr] - yj0; dy0 = (dy0 < 0) ? -dy0 : dy0;
                    int dx0 = xi[m][rr] - xj0; dx0 = (dx0 < 0) ? -dx0 : dx0;
                    int dy1 = yi[m][rr] - yj1; dy1 = (dy1 < 0) ? -dy1 : dy1;
                    int dx1 = xi[m][rr] - xj1; dx1 = (dx1 < 0) ? -dx1 : dx1;
                    float s0 = fmaf(lam, __bfloat162float(dmt[dy0 * WW + dx0]), S[m][n][rr * 2 + 0] * QK_SCALE);
                    float s1 = fmaf(lam, __bfloat162float(dmt[dy1 * WW + dx1]), S[m][n][rr * 2 + 1] * QK_SCALE);
                    p[rr * 2 + 0] = __expf(s0);
                    p[rr * 2 + 1] = __expf(s1);
                    rsum[m][rr] += p[rr * 2 + 0] + p[rr * 2 + 1];
                }
                uint32_t lo, hi;
                asm("cvt.rn.bf16x2.f32 %0, %1, %2;" : "=r"(lo) : "f"(p[1]), "f"(p[0]));
                asm("cvt.rn.bf16x2.f32 %0, %1, %2;" : "=r"(hi) : "f"(p[3]), "f"(p[2]));
                pa[m][n >> 1][(n & 1) * 2 + 0] = lo;   // a0 or a2
                pa[m][n >> 1][(n & 1) * 2 + 1] = hi;   // a1 or a3
            }
        }

        // --- O += P @ V : B = V^T via ldmatrix.trans ---
        {
            const int vrow = (lane & 7) + ((lane >> 3) & 1) * 8;  // key row
            const int vcol = ((lane >> 4) & 1) * 8;               // dim half
            #pragma unroll
            for (int k2 = 0; k2 < 4; k2++) {
                #pragma unroll
                for (int dp = 0; dp < 2; dp++) {
                    uint32_t vf[4];
                    uint32_t a = smem_u32(Vs + (k2 * 16 + vrow) * QPAD + dp * 16 + vcol);
                    ldmx4t(vf[0], vf[1], vf[2], vf[3], a);
                    #pragma unroll
                    for (int m = 0; m < 2; m++) {
                        mma16816(o[m][2 * dp],     pa[m][k2], vf);
                        mma16816(o[m][2 * dp + 1], pa[m][k2], vf + 2);
                    }
                }
            }
        }
    }

    // reduce row sums across the 4 lanes sharing each row
    #pragma unroll
    for (int m = 0; m < 2; m++)
        #pragma unroll
        for (int rr = 0; rr < 2; rr++) {
            float s = rsum[m][rr];
            s += __shfl_xor_sync(0xFFFFFFFF, s, 1);
            s += __shfl_xor_sync(0xFFFFFFFF, s, 2);
            rsum[m][rr] = 1.0f / s;
        }

    // normalize + store O
    #pragma unroll
    for (int m = 0; m < 2; m++)
        #pragma unroll
        for (int rr = 0; rr < 2; rr++) {
            const int grow = rowBase + warp * 32 + m * 16 + (lane >> 2) + rr * 8;
            float* od = g_O + (size_t)(b * HWP + grow) * DM + h * DK;
            const float inv = rsum[m][rr];
            #pragma unroll
            for (int n = 0; n < 4; n++) {
                float2 v;
                v.x = o[m][n][rr * 2 + 0] * inv;
                v.y = o[m][n][rr * 2 + 1] * inv;
                *(float2*)(od + n * 8 + c2) = v;
            }
        }
}

// ---------------------------------------------------------------------------
// Kernel 3: output projection + residual:  y = x + bo + gamma * (Wo @ O)
// ---------------------------------------------------------------------------
__global__ __launch_bounds__(256) void outproj_kernel(
    const float* __restrict__ x, const float* __restrict__ Wo,
    const float* __restrict__ bo, const float* __restrict__ gamma_p,
    float* __restrict__ out)
{
    __shared__ float Os[64][33];
    __shared__ float Wos[64][33];

    const int b     = blockIdx.z;
    const int pBase = blockIdx.x * 64;
    const int cBase = blockIdx.y * 64;
    const int tid   = threadIdx.x;

    const int pl = (tid & 15);
    const int cg = (tid >> 4) * 4;
    const float gamma = *gamma_p;

    float acc[4][4] = {};

    for (int k0 = 0; k0 < DM; k0 += 32) {
        #pragma unroll
        for (int i = tid; i < 64 * 32; i += 256) {
            int r = i >> 5, k = i & 31;
            Os[r][k]  = g_O[((size_t)b * HWP + pBase + r) * DM + k0 + k];
            Wos[r][k] = Wo[(cBase + r) * DM + k0 + k];
        }
        __syncthreads();

        #pragma unroll
        for (int k = 0; k < 32; k++) {
            float a[4], w[4];
            #pragma unroll
            for (int i = 0; i < 4; i++) a[i] = Os[pl + 16 * i][k];
            #pragma unroll
            for (int j = 0; j < 4; j++) w[j] = Wos[cg + j][k];
            #pragma unroll
            for (int i = 0; i < 4; i++)
                #pragma unroll
                for (int j = 0; j < 4; j++)
                    acc[i][j] += a[i] * w[j];
        }
        __syncthreads();
    }

    #pragma unroll
    for (int j = 0; j < 4; j++) {
        const int c = cBase + cg + j;
        const float bias = bo[c];
        #pragma unroll
        for (int i = 0; i < 4; i++) {
            const int p = pBase + pl + 16 * i;
            const size_t idx = (size_t)b * CC * HWP + (size_t)c * HWP + p;
            out[idx] = x[idx] + gamma * acc[i][j] + bias;
        }
    }
}

// ---------------------------------------------------------------------------
extern "C" void kernel_launch(void* const* d_in, const int* in_sizes, int n_in,
                              void* d_out, int out_size)
{
    (void)in_sizes; (void)n_in; (void)out_size;
    const float* x   = (const float*)d_in[0];
    const float* Wq  = (const float*)d_in[1];
    const float* bq  = (const float*)d_in[2];
    const float* Wk  = (const float*)d_in[3];
    const float* bk  = (const float*)d_in[4];
    const float* Wv  = (const float*)d_in[5];
    const float* bv  = (const float*)d_in[6];
    const float* Wo  = (const float*)d_in[7];
    const float* bo  = (const float*)d_in[8];
    const float* lam = (const float*)d_in[9];
    const float* gam = (const float*)d_in[10];
    float* out = (float*)d_out;

    dim3 g1(HWP / 64, DM / 64, BB);
    qkv_kernel<<<g1, 256>>>(x, Wq, bq, Wk, bk, Wv, bv);

    dim3 g2(HWP / 128, BB * NH);
    attn_mma_kernel<<<g2, 128>>>(lam);

    dim3 g3(HWP / 64, CC / 64, BB);
    outproj_kernel<<<g3, 256>>>(x, Wo, bo, gam, out);
}

// round 4
// speedup vs baseline: 4.0323x; 1.3189x over previous
#include <cuda_runtime.h>
#include <cuda_bf16.h>
#include <cstdint>

#define BB 2
#define CC 256
#define HH 48
#define WW 48
#define HWP 2304
#define DM 256
#define NH 8
#define DK 32
#define QK_SCALE 0.17677669529663689f   // 1/sqrt(32)
#define QPAD 40                          // padded row pitch (bf16) = 80B

// ---------------- scratch (allocation-free) ----------------
__device__ __nv_bfloat16 g_Qb[BB * HWP * DM];   // (b, p, d) bf16
__device__ __nv_bfloat16 g_Kb[BB * HWP * DM];   // (b, p, d) bf16
__device__ __nv_bfloat16 g_Vb[BB * HWP * DM];   // (b, p, d) bf16
__device__ float         g_O [BB * HWP * DM];   // (b, p, d) f32

// ---------------- helpers ----------------
__device__ __forceinline__ uint32_t smem_u32(const void* p) {
    uint32_t a;
    asm("{ .reg .u64 t; cvta.to.shared.u64 t, %1; cvt.u32.u64 %0, t; }" : "=r"(a) : "l"(p));
    return a;
}
__device__ __forceinline__ void ldmx4(uint32_t& r0, uint32_t& r1, uint32_t& r2, uint32_t& r3, uint32_t a) {
    asm volatile("ldmatrix.sync.aligned.m8n8.x4.shared.b16 {%0,%1,%2,%3}, [%4];"
                 : "=r"(r0), "=r"(r1), "=r"(r2), "=r"(r3) : "r"(a));
}
__device__ __forceinline__ void ldmx4t(uint32_t& r0, uint32_t& r1, uint32_t& r2, uint32_t& r3, uint32_t a) {
    asm volatile("ldmatrix.sync.aligned.m8n8.x4.trans.shared.b16 {%0,%1,%2,%3}, [%4];"
                 : "=r"(r0), "=r"(r1), "=r"(r2), "=r"(r3) : "r"(a));
}
__device__ __forceinline__ void mma16816(float* c, const uint32_t* a, const uint32_t* b) {
    asm volatile("mma.sync.aligned.m16n8k16.row.col.f32.bf16.bf16.f32 "
                 "{%0,%1,%2,%3},{%4,%5,%6,%7},{%8,%9},{%0,%1,%2,%3};"
                 : "+f"(c[0]), "+f"(c[1]), "+f"(c[2]), "+f"(c[3])
                 : "r"(a[0]), "r"(a[1]), "r"(a[2]), "r"(a[3]), "r"(b[0]), "r"(b[1]));
}
__device__ __forceinline__ uint32_t pack_bf16x2(float lo, float hi) {
    uint32_t r;
    asm("cvt.rn.bf16x2.f32 %0, %1, %2;" : "=r"(r) : "f"(hi), "f"(lo));
    return r;
}

// ---------------------------------------------------------------------------
// Kernel 1: HMMA fused QKV projection + pe + bias -> bf16 scratch (p,d)
// CTA = 256 thr (8 warps): M=128 pixels x N=64 dims, all 3 matrices.
// Grid = (36 pixel-tiles, 4 dim-tiles).
// ---------------------------------------------------------------------------
__global__ __launch_bounds__(256) void qkv_mma_kernel(
    const float* __restrict__ x,
    const float* __restrict__ Wq, const float* __restrict__ bq,
    const float* __restrict__ Wk, const float* __restrict__ bk,
    const float* __restrict__ Wv, const float* __restrict__ bv)
{
    __shared__ __nv_bfloat16 xs[128 * QPAD];          // A: [p][c] staged transpose
    __shared__ __nv_bfloat16 ws[3][64 * QPAD];        // B: [d][c] natural
    __shared__ float pes[48 * 64];                    // pe[coord][dloc]

    const int tid  = threadIdx.x;
    const int warp = tid >> 5;
    const int lane = tid & 31;

    const int gp    = blockIdx.x * 128;
    const int b     = gp / HWP;
    const int pb    = gp - b * HWP;
    const int dBase = blockIdx.y * 64;
    const bool use_y = (dBase >= 128);

    // pe table: coord 0..47 x dloc 0..63
    for (int i = tid; i < 48 * 64; i += 256) {
        const int coord = i >> 6;
        const int dloc  = i & 63;
        const int dl    = (dBase + dloc) - (use_y ? 128 : 0);
        const float freq = __expf(-(float)(dl >> 1) * 0.14391156642875743f);
        const float arg  = (float)coord * freq;
        pes[i] = (dl & 1) ? __cosf(arg) : __sinf(arg);
    }

    const int mw = warp >> 1;          // m-group (0..3) -> rows mw*32
    const int nw = warp & 1;           // n-group (0..1) -> dims nw*32

    float acc[3][2][4][4] = {};        // [mat][mtile][n8][frag]

    for (int c0 = 0; c0 < CC; c0 += 32) {
        __syncthreads();
        // x chunk: 32 c x 128 p, staged transposed [p][c] with f32->bf16
        #pragma unroll
        for (int i = tid; i < 32 * 128; i += 256) {
            const int c  = i >> 7;
            const int pp = i & 127;
            const float v = x[((size_t)b * CC + c0 + c) * HWP + pb + pp];
            xs[pp * QPAD + c] = __float2bfloat16(v);
        }
        // weight chunks: 64 d x 32 c natural
        #pragma unroll
        for (int i = tid; i < 64 * 32; i += 256) {
            const int dd = i >> 5;
            const int cc = i & 31;
            const int widx = (dBase + dd) * CC + c0 + cc;
            ws[0][dd * QPAD + cc] = __float2bfloat16(Wq[widx]);
            ws[1][dd * QPAD + cc] = __float2bfloat16(Wk[widx]);
            ws[2][dd * QPAD + cc] = __float2bfloat16(Wv[widx]);
        }
        __syncthreads();

        const int arow = (lane & 7) + ((lane >> 3) & 1) * 8;
        const int acol = (lane >> 4) * 8;
        const int brow = (lane & 7) + ((lane >> 4) & 1) * 8;
        const int bcol = ((lane >> 3) & 1) * 8;

        #pragma unroll
        for (int ks = 0; ks < 2; ks++) {
            uint32_t af[2][4];
            #pragma unroll
            for (int mt = 0; mt < 2; mt++) {
                uint32_t a = smem_u32(xs + (mw * 32 + mt * 16 + arow) * QPAD + ks * 16 + acol);
                ldmx4(af[mt][0], af[mt][1], af[mt][2], af[mt][3], a);
            }
            #pragma unroll
            for (int mat = 0; mat < 3; mat++) {
                #pragma unroll
                for (int nt = 0; nt < 2; nt++) {
                    uint32_t bf[4];
                    uint32_t a = smem_u32(ws[mat] + (nw * 32 + nt * 16 + brow) * QPAD + ks * 16 + bcol);
                    ldmx4(bf[0], bf[1], bf[2], bf[3], a);
                    #pragma unroll
                    for (int mt = 0; mt < 2; mt++) {
                        mma16816(acc[mat][mt][2 * nt],     af[mt], bf);
                        mma16816(acc[mat][mt][2 * nt + 1], af[mt], bf + 2);
                    }
                }
            }
        }
    }

    // epilogue: bias + pe (q,k), write bf16x2 to (p,d)
    const int c2 = 2 * (lane & 3);
    #pragma unroll
    for (int mt = 0; mt < 2; mt++) {
        #pragma unroll
        for (int rr = 0; rr < 2; rr++) {
            const int ploc = mw * 32 + mt * 16 + (lane >> 2) + rr * 8;
            const int p    = pb + ploc;
            const int coord = use_y ? (p / WW) : (p % WW);
            const size_t rowIdx = ((size_t)b * HWP + p) * DM + dBase;
            #pragma unroll
            for (int n = 0; n < 4; n++) {
                const int dloc = nw * 32 + n * 8 + c2;
                const int d    = dBase + dloc;
                const float pe0 = pes[coord * 64 + dloc];
                const float pe1 = pes[coord * 64 + dloc + 1];
                const float bq0 = bq[d], bq1 = bq[d + 1];
                const float bk0 = bk[d], bk1 = bk[d + 1];
                const float bv0 = bv[d], bv1 = bv[d + 1];
                const float q0 = acc[0][mt][n][rr * 2 + 0] + bq0 + pe0;
                const float q1 = acc[0][mt][n][rr * 2 + 1] + bq1 + pe1;
                const float k0 = acc[1][mt][n][rr * 2 + 0] + bk0 + pe0;
                const float k1 = acc[1][mt][n][rr * 2 + 1] + bk1 + pe1;
                const float v0 = acc[2][mt][n][rr * 2 + 0] + bv0;
                const float v1 = acc[2][mt][n][rr * 2 + 1] + bv1;
                *(uint32_t*)(g_Qb + rowIdx + dloc) = pack_bf16x2(q0, q1);
                *(uint32_t*)(g_Kb + rowIdx + dloc) = pack_bf16x2(k0, k1);
                *(uint32_t*)(g_Vb + rowIdx + dloc) = pack_bf16x2(v0, v1);
            }
        }
    }
}

// ---------------------------------------------------------------------------
// Kernel 2: HMMA flash attention (unchanged from R3).
// ---------------------------------------------------------------------------
__global__ __launch_bounds__(128) void attn_mma_kernel(const float* __restrict__ lambda_p)
{
    __shared__ __nv_bfloat16 Qs[128 * QPAD];
    __shared__ __nv_bfloat16 Ks[64 * QPAD];
    __shared__ __nv_bfloat16 Vs[64 * QPAD];
    __shared__ __nv_bfloat16 dmt[HH * WW];

    const int tid  = threadIdx.x;
    const int warp = tid >> 5;
    const int lane = tid & 31;
    const int b    = blockIdx.y >> 3;
    const int h    = blockIdx.y & 7;
    const int rowBase = blockIdx.x * 128;
    const float lam = *lambda_p;

    for (int i = tid; i < HH * WW; i += 128) {
        int dy = i / WW, dx = i % WW;
        dmt[i] = __float2bfloat16(__expf(-sqrtf((float)(dy * dy + dx * dx))));
    }

    {
        const __nv_bfloat16* qsrc = g_Qb + (size_t)(b * HWP + rowBase) * DM + h * DK;
        #pragma unroll
        for (int c = tid; c < 512; c += 128) {
            int r = c >> 2, q = c & 3;
            uint4 v = *(const uint4*)(qsrc + (size_t)r * DM + q * 8);
            *(uint4*)(Qs + r * QPAD + q * 8) = v;
        }
    }
    __syncthreads();

    uint32_t qa[2][2][4];
    {
        const int arow = (lane & 7) + ((lane >> 3) & 1) * 8;
        const int acol = (lane >> 4) * 8;
        #pragma unroll
        for (int m = 0; m < 2; m++)
            #pragma unroll
            for (int ks = 0; ks < 2; ks++) {
                uint32_t a = smem_u32(Qs + (warp * 32 + m * 16 + arow) * QPAD + ks * 16 + acol);
                ldmx4(qa[m][ks][0], qa[m][ks][1], qa[m][ks][2], qa[m][ks][3], a);
            }
    }

    int yi[2][2], xi[2][2];
    #pragma unroll
    for (int m = 0; m < 2; m++)
        #pragma unroll
        for (int rr = 0; rr < 2; rr++) {
            int g = rowBase + warp * 32 + m * 16 + (lane >> 2) + rr * 8;
            yi[m][rr] = g / WW;
            xi[m][rr] = g - yi[m][rr] * WW;
        }

    float o[2][4][4] = {};
    float rsum[2][2] = {};
    const int c2 = 2 * (lane & 3);

    for (int jt = 0; jt < HWP; jt += 64) {
        __syncthreads();
        {
            const __nv_bfloat16* kb = g_Kb + (size_t)(b * HWP + jt) * DM + h * DK;
            const __nv_bfloat16* vb = g_Vb + (size_t)(b * HWP + jt) * DM + h * DK;
            #pragma unroll
            for (int c = tid; c < 256; c += 128) {
                int r = c >> 2, q = c & 3;
                *(uint4*)(Ks + r * QPAD + q * 8) = *(const uint4*)(kb + (size_t)r * DM + q * 8);
                *(uint4*)(Vs + r * QPAD + q * 8) = *(const uint4*)(vb + (size_t)r * DM + q * 8);
            }
        }
        __syncthreads();

        float S[2][8][4] = {};
        {
            const int brow = (lane & 7) + ((lane >> 4) & 1) * 8;
            const int bcol = ((lane >> 3) & 1) * 8;
            #pragma unroll
            for (int np = 0; np < 4; np++) {
                #pragma unroll
                for (int ks = 0; ks < 2; ks++) {
                    uint32_t kf[4];
                    uint32_t a = smem_u32(Ks + (np * 16 + brow) * QPAD + ks * 16 + bcol);
                    ldmx4(kf[0], kf[1], kf[2], kf[3], a);
                    #pragma unroll
                    for (int m = 0; m < 2; m++) {
                        mma16816(S[m][2 * np],     qa[m][ks], kf);
                        mma16816(S[m][2 * np + 1], qa[m][ks], kf + 2);
                    }
                }
            }
        }

        uint32_t pa[2][4][4];
        #pragma unroll
        for (int n = 0; n < 8; n++) {
            const int jg0 = jt + n * 8 + c2;
            const int yj0 = jg0 / WW, xj0 = jg0 - yj0 * WW;
            const int jg1 = jg0 + 1;
            const int yj1 = jg1 / WW, xj1 = jg1 - yj1 * WW;
            #pragma unroll
            for (int m = 0; m < 2; m++) {
                float p[4];
                #pragma unroll
                for (int rr = 0; rr < 2; rr++) {
                    int dy0 = yi[m][rr] - yj0; dy0 = (dy0 < 0) ? -dy0 : dy0;
                    int dx0 = xi[m][rr] - xj0; dx0 = (dx0 < 0) ? -dx0 : dx0;
                    int dy1 = yi[m][rr] - yj1; dy1 = (dy1 < 0) ? -dy1 : dy1;
                    int dx1 = xi[m][rr] - xj1; dx1 = (dx1 < 0) ? -dx1 : dx1;
                    float s0 = fmaf(lam, __bfloat162float(dmt[dy0 * WW + dx0]), S[m][n][rr * 2 + 0] * QK_SCALE);
                    float s1 = fmaf(lam, __bfloat162float(dmt[dy1 * WW + dx1]), S[m][n][rr * 2 + 1] * QK_SCALE);
                    p[rr * 2 + 0] = __expf(s0);
                    p[rr * 2 + 1] = __expf(s1);
                    rsum[m][rr] += p[rr * 2 + 0] + p[rr * 2 + 1];
                }
                uint32_t lo, hi;
                asm("cvt.rn.bf16x2.f32 %0, %1, %2;" : "=r"(lo) : "f"(p[1]), "f"(p[0]));
                asm("cvt.rn.bf16x2.f32 %0, %1, %2;" : "=r"(hi) : "f"(p[3]), "f"(p[2]));
                pa[m][n >> 1][(n & 1) * 2 + 0] = lo;
                pa[m][n >> 1][(n & 1) * 2 + 1] = hi;
            }
        }

        {
            const int vrow = (lane & 7) + ((lane >> 3) & 1) * 8;
            const int vcol = ((lane >> 4) & 1) * 8;
            #pragma unroll
            for (int k2 = 0; k2 < 4; k2++) {
                #pragma unroll
                for (int dp = 0; dp < 2; dp++) {
                    uint32_t vf[4];
                    uint32_t a = smem_u32(Vs + (k2 * 16 + vrow) * QPAD + dp * 16 + vcol);
                    ldmx4t(vf[0], vf[1], vf[2], vf[3], a);
                    #pragma unroll
                    for (int m = 0; m < 2; m++) {
                        mma16816(o[m][2 * dp],     pa[m][k2], vf);
                        mma16816(o[m][2 * dp + 1], pa[m][k2], vf + 2);
                    }
                }
            }
        }
    }

    #pragma unroll
    for (int m = 0; m < 2; m++)
        #pragma unroll
        for (int rr = 0; rr < 2; rr++) {
            float s = rsum[m][rr];
            s += __shfl_xor_sync(0xFFFFFFFF, s, 1);
            s += __shfl_xor_sync(0xFFFFFFFF, s, 2);
            rsum[m][rr] = 1.0f / s;
        }

    #pragma unroll
    for (int m = 0; m < 2; m++)
        #pragma unroll
        for (int rr = 0; rr < 2; rr++) {
            const int grow = rowBase + warp * 32 + m * 16 + (lane >> 2) + rr * 8;
            float* od = g_O + (size_t)(b * HWP + grow) * DM + h * DK;
            const float inv = rsum[m][rr];
            #pragma unroll
            for (int n = 0; n < 4; n++) {
                float2 v;
                v.x = o[m][n][rr * 2 + 0] * inv;
                v.y = o[m][n][rr * 2 + 1] * inv;
                *(float2*)(od + n * 8 + c2) = v;
            }
        }
}

// ---------------------------------------------------------------------------
// Kernel 3: HMMA output projection + residual.
// C[m=c][n=p]: A = Wo[c][dm], B = O[p][dm] (both natural, non-trans).
// CTA = 256 thr: M=64 c x N=128 p. Grid = (36 p-tiles, 4 c-tiles).
// ---------------------------------------------------------------------------
__global__ __launch_bounds__(256) void outproj_mma_kernel(
    const float* __restrict__ x, const float* __restrict__ Wo,
    const float* __restrict__ bo, const float* __restrict__ gamma_p,
    float* __restrict__ out)
{
    __shared__ __nv_bfloat16 wos[64 * QPAD];    // [c][dm]
    __shared__ __nv_bfloat16 obs[128 * QPAD];   // [p][dm]

    const int tid  = threadIdx.x;
    const int warp = tid >> 5;
    const int lane = tid & 31;

    const int gp    = blockIdx.x * 128;
    const int b     = gp / HWP;
    const int pb    = gp - b * HWP;
    const int cBase = blockIdx.y * 64;
    const float gamma = *gamma_p;

    const int cw = warp & 1;     // c-group: rows cw*32
    const int pw = warp >> 1;    // p-group: cols pw*32

    float acc[2][4][4] = {};

    for (int k0 = 0; k0 < DM; k0 += 32) {
        __syncthreads();
        #pragma unroll
        for (int i = tid; i < 64 * 32; i += 256) {
            const int r = i >> 5, cc = i & 31;
            wos[r * QPAD + cc] = __float2bfloat16(Wo[(cBase + r) * DM + k0 + cc]);
        }
        #pragma unroll
        for (int i = tid; i < 128 * 32; i += 256) {
            const int r = i >> 5, cc = i & 31;
            obs[r * QPAD + cc] = __float2bfloat16(g_O[((size_t)b * HWP + pb + r) * DM + k0 + cc]);
        }
        __syncthreads();

        const int arow = (lane & 7) + ((lane >> 3) & 1) * 8;
        const int acol = (lane >> 4) * 8;
        const int brow = (lane & 7) + ((lane >> 4) & 1) * 8;
        const int bcol = ((lane >> 3) & 1) * 8;

        #pragma unroll
        for (int ks = 0; ks < 2; ks++) {
            uint32_t af[2][4];
            #pragma unroll
            for (int mt = 0; mt < 2; mt++) {
                uint32_t a = smem_u32(wos + (cw * 32 + mt * 16 + arow) * QPAD + ks * 16 + acol);
                ldmx4(af[mt][0], af[mt][1], af[mt][2], af[mt][3], a);
            }
            #pragma unroll
            for (int nt = 0; nt < 2; nt++) {
                uint32_t bf[4];
                uint32_t a = smem_u32(obs + (pw * 32 + nt * 16 + brow) * QPAD + ks * 16 + bcol);
                ldmx4(bf[0], bf[1], bf[2], bf[3], a);
                #pragma unroll
                for (int mt = 0; mt < 2; mt++) {
                    mma16816(acc[mt][2 * nt],     af[mt], bf);
                    mma16816(acc[mt][2 * nt + 1], af[mt], bf + 2);
                }
            }
        }
    }

    const int c2 = 2 * (lane & 3);
    #pragma unroll
    for (int mt = 0; mt < 2; mt++) {
        #pragma unroll
        for (int rr = 0; rr < 2; rr++) {
            const int c = cBase + cw * 32 + mt * 16 + (lane >> 2) + rr * 8;
            const float bias = bo[c];
            #pragma unroll
            for (int n = 0; n < 4; n++) {
                const int p = pb + pw * 32 + n * 8 + c2;
                const size_t idx = (size_t)b * CC * HWP + (size_t)c * HWP + p;
                float2 xv = *(const float2*)(x + idx);
                float2 r;
                r.x = xv.x + gamma * acc[mt][n][rr * 2 + 0] + bias;
                r.y = xv.y + gamma * acc[mt][n][rr * 2 + 1] + bias;
                *(float2*)(out + idx) = r;
            }
        }
    }
}

// ---------------------------------------------------------------------------
extern "C" void kernel_launch(void* const* d_in, const int* in_sizes, int n_in,
                              void* d_out, int out_size)
{
    (void)in_sizes; (void)n_in; (void)out_size;
    const float* x   = (const float*)d_in[0];
    const float* Wq  = (const float*)d_in[1];
    const float* bq  = (const float*)d_in[2];
    const float* Wk  = (const float*)d_in[3];
    const float* bk  = (const float*)d_in[4];
    const float* Wv  = (const float*)d_in[5];
    const float* bv  = (const float*)d_in[6];
    const float* Wo  = (const float*)d_in[7];
    const float* bo  = (const float*)d_in[8];
    const float* lam = (const float*)d_in[9];
    const float* gam = (const float*)d_in[10];
    float* out = (float*)d_out;

    dim3 g1(BB * HWP / 128, DM / 64);
    qkv_mma_kernel<<<g1, 256>>>(x, Wq, bq, Wk, bk, Wv, bv);

    dim3 g2(HWP / 128, BB * NH);
    attn_mma_kernel<<<g2, 128>>>(lam);

    dim3 g3(BB * HWP / 128, CC / 64);
    outproj_mma_kernel<<<g3, 256>>>(x, Wo, bo, gam, out);
}

// round 7
// speedup vs baseline: 5.4817x; 1.3594x over previous
#include <cuda_runtime.h>
#include <cuda_bf16.h>
#include <cstdint>

#define BB 2
#define CC 256
#define HH 48
#define WW 48
#define HWP 2304
#define DM 256
#define NH 8
#define DK 32
#define QK_SCALE 0.17677669529663689f   // 1/sqrt(32)
#define LOG2E 1.4426950408889634f
#define QPAD 40                          // K/V/Q/A pitch (bf16) = 80B (16B multiple)
#define WPAD 40                          // W pitch (bf16) = 80B
#define BPITCH 72                        // bias tile pitch (bytes, fp8; scalar loads only)

// ---------------- scratch (allocation-free) ----------------
__device__ __nv_bfloat16 g_Qb[BB * HWP * DM];    // (b, p, d)
__device__ __nv_bfloat16 g_Kb[BB * HWP * DM];
__device__ __nv_bfloat16 g_Vb[BB * HWP * DM];
__device__ float         g_O [BB * HWP * DM];
__device__ __nv_bfloat16 g_xb[BB * HWP * CC];    // x transposed (b, p, c) bf16
__device__ __nv_bfloat16 g_Wqb[DM * CC];
__device__ __nv_bfloat16 g_Wkb[DM * CC];
__device__ __nv_bfloat16 g_Wvb[DM * CC];
__device__ unsigned char g_biasF8[HWP * HWP];    // lam*dm*log2e, e4m3

// ---------------- helpers ----------------
__device__ __forceinline__ uint32_t smem_u32(const void* p) {
    uint32_t a;
    asm("{ .reg .u64 t; cvta.to.shared.u64 t, %1; cvt.u32.u64 %0, t; }" : "=r"(a) : "l"(p));
    return a;
}
__device__ __forceinline__ void ldmx4(uint32_t& r0, uint32_t& r1, uint32_t& r2, uint32_t& r3, uint32_t a) {
    asm volatile("ldmatrix.sync.aligned.m8n8.x4.shared.b16 {%0,%1,%2,%3}, [%4];"
                 : "=r"(r0), "=r"(r1), "=r"(r2), "=r"(r3) : "r"(a));
}
__device__ __forceinline__ void ldmx4t(uint32_t& r0, uint32_t& r1, uint32_t& r2, uint32_t& r3, uint32_t a) {
    asm volatile("ldmatrix.sync.aligned.m8n8.x4.trans.shared.b16 {%0,%1,%2,%3}, [%4];"
                 : "=r"(r0), "=r"(r1), "=r"(r2), "=r"(r3) : "r"(a));
}
__device__ __forceinline__ void mma16816(float* c, const uint32_t* a, const uint32_t* b) {
    asm volatile("mma.sync.aligned.m16n8k16.row.col.f32.bf16.bf16.f32 "
                 "{%0,%1,%2,%3},{%4,%5,%6,%7},{%8,%9},{%0,%1,%2,%3};"
                 : "+f"(c[0]), "+f"(c[1]), "+f"(c[2]), "+f"(c[3])
                 : "r"(a[0]), "r"(a[1]), "r"(a[2]), "r"(a[3]), "r"(b[0]), "r"(b[1]));
}
__device__ __forceinline__ uint32_t pack_bf16x2(float lo, float hi) {
    uint32_t r;
    asm("cvt.rn.bf16x2.f32 %0, %1, %2;" : "=r"(r) : "f"(hi), "f"(lo));
    return r;
}
__device__ __forceinline__ float ex2f(float x) {
    float r;
    asm("ex2.approx.ftz.f32 %0, %1;" : "=f"(r) : "f"(x));
    return r;
}
#define CPA16(dst, src) asm volatile("cp.async.cg.shared.global [%0], [%1], 16;" :: "r"(dst), "l"(src))
#define CPA8(dst, src)  asm volatile("cp.async.ca.shared.global [%0], [%1], 8;"  :: "r"(dst), "l"(src))
#define CPA_COMMIT()    asm volatile("cp.async.commit_group;")
#define CPA_WAIT0()     asm volatile("cp.async.wait_group 0;")

// ---------------------------------------------------------------------------
// Prep 1: convert Wq/Wk/Wv fp32 -> bf16 (natural [d][c] layout).
// ---------------------------------------------------------------------------
__global__ __launch_bounds__(256) void convw_kernel(
    const float* __restrict__ Wq, const float* __restrict__ Wk, const float* __restrict__ Wv)
{
    const int idx = blockIdx.x * 256 + threadIdx.x;   // 98304 u32 outputs
    const int mat = idx >> 15;
    const int off = idx & 32767;
    const float* s = (mat == 0) ? Wq : ((mat == 1) ? Wk : Wv);
    uint32_t* d = (uint32_t*)((mat == 0) ? g_Wqb : ((mat == 1) ? g_Wkb : g_Wvb));
    d[off] = pack_bf16x2(s[off * 2], s[off * 2 + 1]);
}

// ---------------------------------------------------------------------------
// Prep 2: transpose+convert x (b,c,p) fp32 -> g_xb (b,p,c) bf16.
// ---------------------------------------------------------------------------
__global__ __launch_bounds__(256) void xt_kernel(const float* __restrict__ x)
{
    __shared__ float ts[64][65];
    const int b  = blockIdx.z;
    const int pB = blockIdx.x * 64;
    const int cB = blockIdx.y * 64;
    #pragma unroll
    for (int i = threadIdx.x; i < 4096; i += 256) {
        const int c = i >> 6, p = i & 63;
        ts[c][p] = x[((size_t)b * CC + cB + c) * HWP + pB + p];
    }
    __syncthreads();
    #pragma unroll
    for (int i = threadIdx.x; i < 2048; i += 256) {
        const int p = i >> 5, q = i & 31;
        *((uint32_t*)g_xb + ((size_t)(b * HWP + pB + p) * CC + cB) / 2 + q) =
            pack_bf16x2(ts[2 * q][p], ts[2 * q + 1][p]);
    }
}

// ---------------------------------------------------------------------------
// Prep 3: bias matrix T[i][j] = lam * exp(-dist(i,j)) * log2e, e4m3 fp8.
// ---------------------------------------------------------------------------
__global__ __launch_bounds__(256) void bias_kernel(const float* __restrict__ lam_p)
{
    const int idx = blockIdx.x * 256 + threadIdx.x;   // HWP*HWP/2 pairs
    const float lam2 = (*lam_p) * LOG2E;
    const int i  = idx / (HWP / 2);
    const int jj = (idx - i * (HWP / 2)) * 2;
    const int yi = i / WW,  xi = i - yi * WW;
    const int yj = jj / WW, xj = jj - yj * WW;
    const int dy  = yi - yj;
    const int dx0 = xi - xj;
    const int dx1 = dx0 - 1;
    const float t0 = lam2 * __expf(-sqrtf((float)(dy * dy + dx0 * dx0)));
    const float t1 = lam2 * __expf(-sqrtf((float)(dy * dy + dx1 * dx1)));
    unsigned short u;
    asm("cvt.rn.satfinite.e4m3x2.f32 %0, %1, %2;" : "=h"(u) : "f"(t1), "f"(t0));
    ((unsigned short*)g_biasF8)[idx] = u;
}

// ---------------------------------------------------------------------------
// Kernel 1: HMMA fused QKV + pe + bias, cp.async double-buffered.
// CTA 256 thr: M=128 pixels x N=64 dims, all 3 matrices. Grid (36, 4).
// ---------------------------------------------------------------------------
__global__ __launch_bounds__(256) void qkv_mma_kernel(
    const float* __restrict__ bq, const float* __restrict__ bk, const float* __restrict__ bv)
{
    __shared__ __align__(16) __nv_bfloat16 As[2][128 * QPAD];      // 2 x 10240B
    __shared__ __align__(16) __nv_bfloat16 Ws[2][3][64 * WPAD];    // 2 x 15360B

    const int tid  = threadIdx.x;
    const int warp = tid >> 5;
    const int lane = tid & 31;

    const int gp    = blockIdx.x * 128;
    const int b     = gp / HWP;
    const int pb    = gp - b * HWP;
    const int dBase = blockIdx.y * 64;
    const bool use_y = (dBase >= 128);

    const uint32_t asA = smem_u32(As);
    const uint32_t wsA = smem_u32(Ws);

    const __nv_bfloat16* gW[3] = { g_Wqb, g_Wkb, g_Wvb };

    auto load_chunk = [&](int s, int c0) {
        // A: 128 rows x 32c (64B/row), pitch 80B; stage stride 10240B
        const char* ab = (const char*)g_xb + ((size_t)(b * HWP + pb) * CC + c0) * 2;
        #pragma unroll
        for (int i = tid; i < 512; i += 256) {
            const int r = i >> 2, q = i & 3;
            CPA16(asA + s * 10240 + r * 80 + q * 16, ab + (size_t)r * (CC * 2) + q * 16);
        }
        // W: 3 x 64 rows x 32c (64B/row), pitch 80B; stage stride 15360B
        #pragma unroll
        for (int i = tid; i < 768; i += 256) {
            const int mat = i / 256;
            const int rem = i - mat * 256;
            const int r = rem >> 2, q = rem & 3;
            const char* wb = (const char*)gW[mat] + ((size_t)(dBase + r) * CC + c0) * 2;
            CPA16(wsA + s * 15360 + mat * 5120 + r * 80 + q * 16, wb + q * 16);
        }
        CPA_COMMIT();
    };

    const int mw = warp >> 1;
    const int nw = warp & 1;

    float acc[3][2][4][4] = {};

    load_chunk(0, 0);

    for (int c = 0; c < 8; c++) {
        CPA_WAIT0();
        __syncthreads();
        if (c < 7) load_chunk((c + 1) & 1, (c + 1) * 32);

        const __nv_bfloat16* Ab = As[c & 1];
        const int s = c & 1;

        const int arow = (lane & 7) + ((lane >> 3) & 1) * 8;
        const int acol = (lane >> 4) * 8;
        const int brow = (lane & 7) + ((lane >> 4) & 1) * 8;
        const int bcol = ((lane >> 3) & 1) * 8;

        #pragma unroll
        for (int ks = 0; ks < 2; ks++) {
            uint32_t af[2][4];
            #pragma unroll
            for (int mt = 0; mt < 2; mt++) {
                uint32_t a = smem_u32(Ab + (mw * 32 + mt * 16 + arow) * QPAD + ks * 16 + acol);
                ldmx4(af[mt][0], af[mt][1], af[mt][2], af[mt][3], a);
            }
            #pragma unroll
            for (int mat = 0; mat < 3; mat++) {
                #pragma unroll
                for (int nt = 0; nt < 2; nt++) {
                    uint32_t bf[4];
                    uint32_t a = smem_u32(&Ws[s][mat][(nw * 32 + nt * 16 + brow) * WPAD + ks * 16 + bcol]);
                    ldmx4(bf[0], bf[1], bf[2], bf[3], a);
                    #pragma unroll
                    for (int mt = 0; mt < 2; mt++) {
                        mma16816(acc[mat][mt][2 * nt],     af[mt], bf);
                        mma16816(acc[mat][mt][2 * nt + 1], af[mt], bf + 2);
                    }
                }
            }
        }
    }

    // pe table built into the (now free) A staging region
    __syncthreads();
    float* pes = (float*)As;   // 48 coords x 64 dims = 12288B
    for (int i = tid; i < 48 * 64; i += 256) {
        const int coord = i >> 6;
        const int dloc  = i & 63;
        const int dl    = (dBase + dloc) - (use_y ? 128 : 0);
        const float freq = __expf(-(float)(dl >> 1) * 0.14391156642875743f);
        const float arg  = (float)coord * freq;
        pes[i] = (dl & 1) ? __cosf(arg) : __sinf(arg);
    }
    __syncthreads();

    const int c2 = 2 * (lane & 3);
    #pragma unroll
    for (int mt = 0; mt < 2; mt++) {
        #pragma unroll
        for (int rr = 0; rr < 2; rr++) {
            const int ploc = mw * 32 + mt * 16 + (lane >> 2) + rr * 8;
            const int p    = pb + ploc;
            const int coord = use_y ? (p / WW) : (p % WW);
            const size_t rowIdx = ((size_t)b * HWP + p) * DM + dBase;
            #pragma unroll
            for (int n = 0; n < 4; n++) {
                const int dloc = nw * 32 + n * 8 + c2;
                const int d    = dBase + dloc;
                const float pe0 = pes[coord * 64 + dloc];
                const float pe1 = pes[coord * 64 + dloc + 1];
                const float q0 = acc[0][mt][n][rr * 2 + 0] + bq[d]     + pe0;
                const float q1 = acc[0][mt][n][rr * 2 + 1] + bq[d + 1] + pe1;
                const float k0 = acc[1][mt][n][rr * 2 + 0] + bk[d]     + pe0;
                const float k1 = acc[1][mt][n][rr * 2 + 1] + bk[d + 1] + pe1;
                const float v0 = acc[2][mt][n][rr * 2 + 0] + bv[d];
                const float v1 = acc[2][mt][n][rr * 2 + 1] + bv[d + 1];
                *(uint32_t*)(g_Qb + rowIdx + dloc) = pack_bf16x2(q0, q1);
                *(uint32_t*)(g_Kb + rowIdx + dloc) = pack_bf16x2(k0, k1);
                *(uint32_t*)(g_Vb + rowIdx + dloc) = pack_bf16x2(v0, v1);
            }
        }
    }
}

// ---------------------------------------------------------------------------
// Kernel 2: HMMA flash attention, cp.async double-buffered K/V/bias.
// CTA 128 thr, 128 query rows. Grid (18, 16). Bias from fp8 table.
// ---------------------------------------------------------------------------
__global__ __launch_bounds__(128) void attn_mma_kernel()
{
    __shared__ __align__(16) __nv_bfloat16 Qs[128 * QPAD];        // 10240B
    __shared__ __align__(16) __nv_bfloat16 Ks[2][64 * QPAD];      // 10240B
    __shared__ __align__(16) __nv_bfloat16 Vs[2][64 * QPAD];      // 10240B
    __shared__ __align__(16) unsigned char Bs[2][128 * BPITCH];   // 18432B

    const int tid  = threadIdx.x;
    const int warp = tid >> 5;
    const int lane = tid & 31;
    const int b    = blockIdx.y >> 3;
    const int h    = blockIdx.y & 7;
    const int rowBase = blockIdx.x * 128;

    const uint32_t ksA = smem_u32(Ks);
    const uint32_t vsA = smem_u32(Vs);
    const uint32_t bsA = smem_u32(Bs);

    auto issue_tile = [&](int t, int s) {
        const int jt = t * 64;
        const char* kb = (const char*)g_Kb + ((size_t)(b * HWP + jt) * DM + h * DK) * 2;
        const char* vb = (const char*)g_Vb + ((size_t)(b * HWP + jt) * DM + h * DK) * 2;
        #pragma unroll
        for (int i = tid; i < 256; i += 128) {
            const int r = i >> 2, q = i & 3;
            CPA16(ksA + s * 5120 + r * 80 + q * 16, kb + (size_t)r * (DM * 2) + q * 16);
            CPA16(vsA + s * 5120 + r * 80 + q * 16, vb + (size_t)r * (DM * 2) + q * 16);
        }
        const unsigned char* bb = g_biasF8 + (size_t)rowBase * HWP + jt;
        #pragma unroll
        for (int i = tid; i < 1024; i += 128) {
            const int r = i >> 3, q = i & 7;
            CPA8(bsA + s * 9216 + r * BPITCH + q * 8, bb + (size_t)r * HWP + q * 8);
        }
        CPA_COMMIT();
    };

    // Q tile
    {
        const __nv_bfloat16* qsrc = g_Qb + (size_t)(b * HWP + rowBase) * DM + h * DK;
        #pragma unroll
        for (int i = tid; i < 512; i += 128) {
            const int r = i >> 2, q = i & 3;
            *(uint4*)(Qs + r * QPAD + q * 8) = *(const uint4*)(qsrc + (size_t)r * DM + q * 8);
        }
    }
    issue_tile(0, 0);
    __syncthreads();

    uint32_t qa[2][2][4];
    {
        const int arow = (lane & 7) + ((lane >> 3) & 1) * 8;
        const int acol = (lane >> 4) * 8;
        #pragma unroll
        for (int m = 0; m < 2; m++)
            #pragma unroll
            for (int ks = 0; ks < 2; ks++) {
                uint32_t a = smem_u32(Qs + (warp * 32 + m * 16 + arow) * QPAD + ks * 16 + acol);
                ldmx4(qa[m][ks][0], qa[m][ks][1], qa[m][ks][2], qa[m][ks][3], a);
            }
    }

    const int c2 = 2 * (lane & 3);
    int boff[2][2];
    #pragma unroll
    for (int m = 0; m < 2; m++)
        #pragma unroll
        for (int rr = 0; rr < 2; rr++)
            boff[m][rr] = (warp * 32 + m * 16 + (lane >> 2) + rr * 8) * BPITCH + c2;

    const float SC2 = QK_SCALE * LOG2E;
    float o[2][4][4] = {};
    float rsum[2][2] = {};

    for (int t = 0; t < HWP / 64; t++) {
        CPA_WAIT0();
        __syncthreads();
        if (t < 35) issue_tile(t + 1, (t + 1) & 1);
        const int s = t & 1;

        // --- S = Q K^T ---
        float S[2][8][4] = {};
        {
            const int brow = (lane & 7) + ((lane >> 4) & 1) * 8;
            const int bcol = ((lane >> 3) & 1) * 8;
            #pragma unroll
            for (int np = 0; np < 4; np++) {
                #pragma unroll
                for (int ks = 0; ks < 2; ks++) {
                    uint32_t kf[4];
                    uint32_t a = smem_u32(&Ks[s][(np * 16 + brow) * QPAD + ks * 16 + bcol]);
                    ldmx4(kf[0], kf[1], kf[2], kf[3], a);
                    #pragma unroll
                    for (int m = 0; m < 2; m++) {
                        mma16816(S[m][2 * np],     qa[m][ks], kf);
                        mma16816(S[m][2 * np + 1], qa[m][ks], kf + 2);
                    }
                }
            }
        }

        // --- P = ex2(S*SC2 + biasF8) ---
        const unsigned char* bbuf = Bs[s];
        uint32_t pa[2][4][4];
        #pragma unroll
        for (int n = 0; n < 8; n++) {
            #pragma unroll
            for (int m = 0; m < 2; m++) {
                float p[4];
                #pragma unroll
                for (int rr = 0; rr < 2; rr++) {
                    const unsigned short hs = *(const unsigned short*)(bbuf + boff[m][rr] + n * 8);
                    uint32_t f2;
                    asm("cvt.rn.f16x2.e4m3x2 %0, %1;" : "=r"(f2) : "h"(hs));
                    float b0, b1;
                    asm("{.reg .b16 l,h; mov.b32 {l,h}, %2; cvt.f32.f16 %0, l; cvt.f32.f16 %1, h;}"
                        : "=f"(b0), "=f"(b1) : "r"(f2));
                    const float p0 = ex2f(fmaf(S[m][n][rr * 2 + 0], SC2, b0));
                    const float p1 = ex2f(fmaf(S[m][n][rr * 2 + 1], SC2, b1));
                    p[rr * 2 + 0] = p0;
                    p[rr * 2 + 1] = p1;
                    rsum[m][rr] += p0 + p1;
                }
                pa[m][n >> 1][(n & 1) * 2 + 0] = pack_bf16x2(p[0], p[1]);
                pa[m][n >> 1][(n & 1) * 2 + 1] = pack_bf16x2(p[2], p[3]);
            }
        }

        // --- O += P @ V ---
        {
            const int vrow = (lane & 7) + ((lane >> 3) & 1) * 8;
            const int vcol = ((lane >> 4) & 1) * 8;
            #pragma unroll
            for (int k2 = 0; k2 < 4; k2++) {
                #pragma unroll
                for (int dp = 0; dp < 2; dp++) {
                    uint32_t vf[4];
                    uint32_t a = smem_u32(&Vs[s][(k2 * 16 + vrow) * QPAD + dp * 16 + vcol]);
                    ldmx4t(vf[0], vf[1], vf[2], vf[3], a);
                    #pragma unroll
                    for (int m = 0; m < 2; m++) {
                        mma16816(o[m][2 * dp],     pa[m][k2], vf);
                        mma16816(o[m][2 * dp + 1], pa[m][k2], vf + 2);
                    }
                }
            }
        }
    }

    #pragma unroll
    for (int m = 0; m < 2; m++)
        #pragma unroll
        for (int rr = 0; rr < 2; rr++) {
            float sv = rsum[m][rr];
            sv += __shfl_xor_sync(0xFFFFFFFF, sv, 1);
            sv += __shfl_xor_sync(0xFFFFFFFF, sv, 2);
            rsum[m][rr] = 1.0f / sv;
        }

    #pragma unroll
    for (int m = 0; m < 2; m++)
        #pragma unroll
        for (int rr = 0; rr < 2; rr++) {
            const int grow = rowBase + warp * 32 + m * 16 + (lane >> 2) + rr * 8;
            float* od = g_O + (size_t)(b * HWP + grow) * DM + h * DK;
            const float inv = rsum[m][rr];
            #pragma unroll
            for (int n = 0; n < 4; n++) {
                float2 v;
                v.x = o[m][n][rr * 2 + 0] * inv;
                v.y = o[m][n][rr * 2 + 1] * inv;
                *(float2*)(od + n * 8 + c2) = v;
            }
        }
}

// ---------------------------------------------------------------------------
// Kernel 3: HMMA output projection + residual.
// ---------------------------------------------------------------------------
__global__ __launch_bounds__(256) void outproj_mma_kernel(
    const float* __restrict__ x, const float* __restrict__ Wo,
    const float* __restrict__ bo, const float* __restrict__ gamma_p,
    float* __restrict__ out)
{
    __shared__ __nv_bfloat16 wos[64 * QPAD];
    __shared__ __nv_bfloat16 obs[128 * QPAD];

    const int tid  = threadIdx.x;
    const int warp = tid >> 5;
    const int lane = tid & 31;

    const int gp    = blockIdx.x * 128;
    const int b     = gp / HWP;
    const int pb    = gp - b * HWP;
    const int cBase = blockIdx.y * 64;
    const float gamma = *gamma_p;

    const int cw = warp & 1;
    const int pw = warp >> 1;

    float acc[2][4][4] = {};

    for (int k0 = 0; k0 < DM; k0 += 32) {
        __syncthreads();
        #pragma unroll
        for (int i = tid; i < 64 * 32; i += 256) {
            const int r = i >> 5, cc = i & 31;
            wos[r * QPAD + cc] = __float2bfloat16(Wo[(cBase + r) * DM + k0 + cc]);
        }
        #pragma unroll
        for (int i = tid; i < 128 * 32; i += 256) {
            const int r = i >> 5, cc = i & 31;
            obs[r * QPAD + cc] = __float2bfloat16(g_O[((size_t)b * HWP + pb + r) * DM + k0 + cc]);
        }
        __syncthreads();

        const int arow = (lane & 7) + ((lane >> 3) & 1) * 8;
        const int acol = (lane >> 4) * 8;
        const int brow = (lane & 7) + ((lane >> 4) & 1) * 8;
        const int bcol = ((lane >> 3) & 1) * 8;

        #pragma unroll
        for (int ks = 0; ks < 2; ks++) {
            uint32_t af[2][4];
            #pragma unroll
            for (int mt = 0; mt < 2; mt++) {
                uint32_t a = smem_u32(wos + (cw * 32 + mt * 16 + arow) * QPAD + ks * 16 + acol);
                ldmx4(af[mt][0], af[mt][1], af[mt][2], af[mt][3], a);
            }
            #pragma unroll
            for (int nt = 0; nt < 2; nt++) {
                uint32_t bf[4];
                uint32_t a = smem_u32(obs + (pw * 32 + nt * 16 + brow) * QPAD + ks * 16 + bcol);
                ldmx4(bf[0], bf[1], bf[2], bf[3], a);
                #pragma unroll
                for (int mt = 0; mt < 2; mt++) {
                    mma16816(acc[mt][2 * nt],     af[mt], bf);
                    mma16816(acc[mt][2 * nt + 1], af[mt], bf + 2);
                }
            }
        }
    }

    const int c2 = 2 * (lane & 3);
    #pragma unroll
    for (int mt = 0; mt < 2; mt++) {
        #pragma unroll
        for (int rr = 0; rr < 2; rr++) {
            const int c = cBase + cw * 32 + mt * 16 + (lane >> 2) + rr * 8;
            const float bias = bo[c];
            #pragma unroll
            for (int n = 0; n < 4; n++) {
                const int p = pb + pw * 32 + n * 8 + c2;
                const size_t idx = (size_t)b * CC * HWP + (size_t)c * HWP + p;
                float2 xv = *(const float2*)(x + idx);
                float2 r;
                r.x = xv.x + gamma * acc[mt][n][rr * 2 + 0] + bias;
                r.y = xv.y + gamma * acc[mt][n][rr * 2 + 1] + bias;
                *(float2*)(out + idx) = r;
            }
        }
    }
}

// ---------------------------------------------------------------------------
extern "C" void kernel_launch(void* const* d_in, const int* in_sizes, int n_in,
                              void* d_out, int out_size)
{
    (void)in_sizes; (void)n_in; (void)out_size;
    const float* x   = (const float*)d_in[0];
    const float* Wq  = (const float*)d_in[1];
    const float* bq  = (const float*)d_in[2];
    const float* Wk  = (const float*)d_in[3];
    const float* bk  = (const float*)d_in[4];
    const float* Wv  = (const float*)d_in[5];
    const float* bv  = (const float*)d_in[6];
    const float* Wo  = (const float*)d_in[7];
    const float* bo  = (const float*)d_in[8];
    const float* lam = (const float*)d_in[9];
    const float* gam = (const float*)d_in[10];
    float* out = (float*)d_out;

    convw_kernel<<<384, 256>>>(Wq, Wk, Wv);
    xt_kernel<<<dim3(HWP / 64, CC / 64, BB), 256>>>(x);
    bias_kernel<<<HWP * HWP / 512, 256>>>(lam);

    qkv_mma_kernel<<<dim3(BB * HWP / 128, DM / 64), 256>>>(bq, bk, bv);

    attn_mma_kernel<<<dim3(HWP / 128, BB * NH), 128>>>();

    outproj_mma_kernel<<<dim3(BB * HWP / 128, CC / 64), 256>>>(x, Wo, bo, gam, out);
}

// round 8
// speedup vs baseline: 5.7189x; 1.0433x over previous
#include <cuda_runtime.h>
#include <cuda_bf16.h>
#include <cstdint>

#define BB 2
#define CC 256
#define HH 48
#define WW 48
#define HWP 2304
#define DM 256
#define NH 8
#define DK 32
#define QK_SCALE 0.17677669529663689f   // 1/sqrt(32)
#define LOG2E 1.4426950408889634f
#define QPAD 40                          // bf16 pitch = 80B (16B multiple)
#define WPAD 40
#define BPITCH 72                        // bias tile pitch (bytes, fp8; scalar loads only)

// ---------------- scratch (allocation-free) ----------------
__device__ __nv_bfloat16 g_Qb[BB * HWP * DM];    // (b, p, d)
__device__ __nv_bfloat16 g_Kb[BB * HWP * DM];
__device__ __nv_bfloat16 g_Vb[BB * HWP * DM];
__device__ __nv_bfloat16 g_Ob[BB * HWP * DM];    // attention out, bf16
__device__ __nv_bfloat16 g_xb[BB * HWP * CC];    // x transposed (b, p, c) bf16
__device__ __nv_bfloat16 g_Wqb[DM * CC];
__device__ __nv_bfloat16 g_Wkb[DM * CC];
__device__ __nv_bfloat16 g_Wvb[DM * CC];
__device__ __nv_bfloat16 g_Wob[CC * DM];
__device__ unsigned char g_biasF8[HWP * HWP];    // lam*dm*log2e, e4m3

// ---------------- helpers ----------------
__device__ __forceinline__ uint32_t smem_u32(const void* p) {
    uint32_t a;
    asm("{ .reg .u64 t; cvta.to.shared.u64 t, %1; cvt.u32.u64 %0, t; }" : "=r"(a) : "l"(p));
    return a;
}
__device__ __forceinline__ void ldmx4(uint32_t& r0, uint32_t& r1, uint32_t& r2, uint32_t& r3, uint32_t a) {
    asm volatile("ldmatrix.sync.aligned.m8n8.x4.shared.b16 {%0,%1,%2,%3}, [%4];"
                 : "=r"(r0), "=r"(r1), "=r"(r2), "=r"(r3) : "r"(a));
}
__device__ __forceinline__ void ldmx4t(uint32_t& r0, uint32_t& r1, uint32_t& r2, uint32_t& r3, uint32_t a) {
    asm volatile("ldmatrix.sync.aligned.m8n8.x4.trans.shared.b16 {%0,%1,%2,%3}, [%4];"
                 : "=r"(r0), "=r"(r1), "=r"(r2), "=r"(r3) : "r"(a));
}
__device__ __forceinline__ void mma16816(float* c, const uint32_t* a, const uint32_t* b) {
    asm volatile("mma.sync.aligned.m16n8k16.row.col.f32.bf16.bf16.f32 "
                 "{%0,%1,%2,%3},{%4,%5,%6,%7},{%8,%9},{%0,%1,%2,%3};"
                 : "+f"(c[0]), "+f"(c[1]), "+f"(c[2]), "+f"(c[3])
                 : "r"(a[0]), "r"(a[1]), "r"(a[2]), "r"(a[3]), "r"(b[0]), "r"(b[1]));
}
__device__ __forceinline__ uint32_t pack_bf16x2(float lo, float hi) {
    uint32_t r;
    asm("cvt.rn.bf16x2.f32 %0, %1, %2;" : "=r"(r) : "f"(hi), "f"(lo));
    return r;
}
__device__ __forceinline__ float ex2f(float x) {
    float r;
    asm("ex2.approx.ftz.f32 %0, %1;" : "=f"(r) : "f"(x));
    return r;
}
#define CPA16(dst, src) asm volatile("cp.async.cg.shared.global [%0], [%1], 16;" :: "r"(dst), "l"(src))
#define CPA8(dst, src)  asm volatile("cp.async.ca.shared.global [%0], [%1], 8;"  :: "r"(dst), "l"(src))
#define CPA_COMMIT()    asm volatile("cp.async.commit_group;")
#define CPA_WAIT0()     asm volatile("cp.async.wait_group 0;")

// ---------------------------------------------------------------------------
// Prep 1: convert Wq/Wk/Wv/Wo fp32 -> bf16.
// ---------------------------------------------------------------------------
__global__ __launch_bounds__(256) void convw_kernel(
    const float* __restrict__ Wq, const float* __restrict__ Wk,
    const float* __restrict__ Wv, const float* __restrict__ Wo)
{
    const int idx = blockIdx.x * 256 + threadIdx.x;   // 131072 u32 outputs
    const int mat = idx >> 15;
    const int off = idx & 32767;
    const float* s = (mat == 0) ? Wq : ((mat == 1) ? Wk : ((mat == 2) ? Wv : Wo));
    uint32_t* d = (uint32_t*)((mat == 0) ? g_Wqb : ((mat == 1) ? g_Wkb : ((mat == 2) ? g_Wvb : g_Wob)));
    d[off] = pack_bf16x2(s[off * 2], s[off * 2 + 1]);
}

// ---------------------------------------------------------------------------
// Prep 2: transpose+convert x (b,c,p) fp32 -> g_xb (b,p,c) bf16.
// ---------------------------------------------------------------------------
__global__ __launch_bounds__(256) void xt_kernel(const float* __restrict__ x)
{
    __shared__ float ts[64][65];
    const int b  = blockIdx.z;
    const int pB = blockIdx.x * 64;
    const int cB = blockIdx.y * 64;
    #pragma unroll
    for (int i = threadIdx.x; i < 4096; i += 256) {
        const int c = i >> 6, p = i & 63;
        ts[c][p] = x[((size_t)b * CC + cB + c) * HWP + pB + p];
    }
    __syncthreads();
    #pragma unroll
    for (int i = threadIdx.x; i < 2048; i += 256) {
        const int p = i >> 5, q = i & 31;
        *((uint32_t*)g_xb + ((size_t)(b * HWP + pB + p) * CC + cB) / 2 + q) =
            pack_bf16x2(ts[2 * q][p], ts[2 * q + 1][p]);
    }
}

// ---------------------------------------------------------------------------
// Prep 3: bias matrix T[i][j] = lam * exp(-dist(i,j)) * log2e, e4m3 fp8.
// ---------------------------------------------------------------------------
__global__ __launch_bounds__(256) void bias_kernel(const float* __restrict__ lam_p)
{
    const int idx = blockIdx.x * 256 + threadIdx.x;   // HWP*HWP/2 pairs
    const float lam2 = (*lam_p) * LOG2E;
    const int i  = idx / (HWP / 2);
    const int jj = (idx - i * (HWP / 2)) * 2;
    const int yi = i / WW,  xi = i - yi * WW;
    const int yj = jj / WW, xj = jj - yj * WW;
    const int dy  = yi - yj;
    const int dx0 = xi - xj;
    const int dx1 = dx0 - 1;
    const float t0 = lam2 * __expf(-sqrtf((float)(dy * dy + dx0 * dx0)));
    const float t1 = lam2 * __expf(-sqrtf((float)(dy * dy + dx1 * dx1)));
    unsigned short u;
    asm("cvt.rn.satfinite.e4m3x2.f32 %0, %1, %2;" : "=h"(u) : "f"(t1), "f"(t0));
    ((unsigned short*)g_biasF8)[idx] = u;
}

// ---------------------------------------------------------------------------
// Kernel 1: HMMA fused QKV + pe + bias, cp.async double-buffered.
// CTA 256 thr: M=64 pixels x N=64 dims, all 3 matrices. Grid (72, 4) -> 2/SM.
// Warps: mw=warp>>2 (2 x 32 rows), nw=warp&3 (4 x 16 dims).
// ---------------------------------------------------------------------------
__global__ __launch_bounds__(256) void qkv_mma_kernel(
    const float* __restrict__ bq, const float* __restrict__ bk, const float* __restrict__ bv)
{
    __shared__ __align__(16) __nv_bfloat16 As[2][64 * QPAD];       // 2 x 5120B
    __shared__ __align__(16) __nv_bfloat16 Ws[2][3][64 * WPAD];    // 2 x 15360B

    const int tid  = threadIdx.x;
    const int warp = tid >> 5;
    const int lane = tid & 31;

    const int gp    = blockIdx.x * 64;
    const int b     = gp / HWP;
    const int pb    = gp - b * HWP;
    const int dBase = blockIdx.y * 64;
    const bool use_y = (dBase >= 128);

    const uint32_t asA = smem_u32(As);
    const uint32_t wsA = smem_u32(Ws);

    const __nv_bfloat16* gW[3] = { g_Wqb, g_Wkb, g_Wvb };

    auto load_chunk = [&](int s, int c0) {
        // A: 64 rows x 32c (64B/row), pitch 80B; stage stride 5120B
        const char* ab = (const char*)g_xb + ((size_t)(b * HWP + pb) * CC + c0) * 2;
        {
            const int i = tid;  // 256 chunks exactly
            const int r = i >> 2, q = i & 3;
            CPA16(asA + s * 5120 + r * 80 + q * 16, ab + (size_t)r * (CC * 2) + q * 16);
        }
        // W: 3 x 64 rows x 32c, pitch 80B; stage stride 15360B
        #pragma unroll
        for (int i = tid; i < 768; i += 256) {
            const int mat = i / 256;
            const int rem = i - mat * 256;
            const int r = rem >> 2, q = rem & 3;
            const char* wb = (const char*)gW[mat] + ((size_t)(dBase + r) * CC + c0) * 2;
            CPA16(wsA + s * 15360 + mat * 5120 + r * 80 + q * 16, wb + q * 16);
        }
        CPA_COMMIT();
    };

    const int mw = warp >> 2;      // 0..1: rows mw*32
    const int nw = warp & 3;       // 0..3: dims nw*16

    float acc[3][2][2][4] = {};    // [mat][mtile][n8][frag]

    load_chunk(0, 0);

    for (int c = 0; c < 8; c++) {
        CPA_WAIT0();
        __syncthreads();
        if (c < 7) load_chunk((c + 1) & 1, (c + 1) * 32);

        const __nv_bfloat16* Ab = As[c & 1];
        const int s = c & 1;

        const int arow = (lane & 7) + ((lane >> 3) & 1) * 8;
        const int acol = (lane >> 4) * 8;
        const int brow = (lane & 7) + ((lane >> 4) & 1) * 8;
        const int bcol = ((lane >> 3) & 1) * 8;

        #pragma unroll
        for (int ks = 0; ks < 2; ks++) {
            uint32_t af[2][4];
            #pragma unroll
            for (int mt = 0; mt < 2; mt++) {
                uint32_t a = smem_u32(Ab + (mw * 32 + mt * 16 + arow) * QPAD + ks * 16 + acol);
                ldmx4(af[mt][0], af[mt][1], af[mt][2], af[mt][3], a);
            }
            #pragma unroll
            for (int mat = 0; mat < 3; mat++) {
                uint32_t bf[4];
                uint32_t a = smem_u32(&Ws[s][mat][(nw * 16 + brow) * WPAD + ks * 16 + bcol]);
                ldmx4(bf[0], bf[1], bf[2], bf[3], a);
                #pragma unroll
                for (int mt = 0; mt < 2; mt++) {
                    mma16816(acc[mat][mt][0], af[mt], bf);
                    mma16816(acc[mat][mt][1], af[mt], bf + 2);
                }
            }
        }
    }

    // pe table (bf16) in the now-free A staging region (6144B <= 10240B)
    __syncthreads();
    __nv_bfloat16* pes = (__nv_bfloat16*)As;   // [coord 0..47][dloc 0..63]
    for (int i = tid; i < 48 * 64; i += 256) {
        const int coord = i >> 6;
        const int dloc  = i & 63;
        const int dl    = (dBase + dloc) - (use_y ? 128 : 0);
        const float freq = __expf(-(float)(dl >> 1) * 0.14391156642875743f);
        const float arg  = (float)coord * freq;
        pes[i] = __float2bfloat16((dl & 1) ? __cosf(arg) : __sinf(arg));
    }
    __syncthreads();

    const int c2 = 2 * (lane & 3);
    #pragma unroll
    for (int mt = 0; mt < 2; mt++) {
        #pragma unroll
        for (int rr = 0; rr < 2; rr++) {
            const int ploc = mw * 32 + mt * 16 + (lane >> 2) + rr * 8;
            const int p    = pb + ploc;
            const int coord = use_y ? (p / WW) : (p % WW);
            const size_t rowIdx = ((size_t)b * HWP + p) * DM + dBase;
            #pragma unroll
            for (int nt = 0; nt < 2; nt++) {
                const int dloc = nw * 16 + nt * 8 + c2;
                const int d    = dBase + dloc;
                const float pe0 = __bfloat162float(pes[coord * 64 + dloc]);
                const float pe1 = __bfloat162float(pes[coord * 64 + dloc + 1]);
                const float q0 = acc[0][mt][nt][rr * 2 + 0] + bq[d]     + pe0;
                const float q1 = acc[0][mt][nt][rr * 2 + 1] + bq[d + 1] + pe1;
                const float k0 = acc[1][mt][nt][rr * 2 + 0] + bk[d]     + pe0;
                const float k1 = acc[1][mt][nt][rr * 2 + 1] + bk[d + 1] + pe1;
                const float v0 = acc[2][mt][nt][rr * 2 + 0] + bv[d];
                const float v1 = acc[2][mt][nt][rr * 2 + 1] + bv[d + 1];
                *(uint32_t*)(g_Qb + rowIdx + dloc) = pack_bf16x2(q0, q1);
                *(uint32_t*)(g_Kb + rowIdx + dloc) = pack_bf16x2(k0, k1);
                *(uint32_t*)(g_Vb + rowIdx + dloc) = pack_bf16x2(v0, v1);
            }
        }
    }
}

// ---------------------------------------------------------------------------
// Kernel 2: HMMA flash attention. CTA 256 thr (8 warps x 16 rows = 128 rows).
// cp.async double-buffered K/V/bias. Grid (18, 16).
// ---------------------------------------------------------------------------
__global__ __launch_bounds__(256) void attn_mma_kernel()
{
    __shared__ __align__(16) __nv_bfloat16 Qs[128 * QPAD];        // 10240B
    __shared__ __align__(16) __nv_bfloat16 Ks[2][64 * QPAD];      // 10240B
    __shared__ __align__(16) __nv_bfloat16 Vs[2][64 * QPAD];      // 10240B
    __shared__ __align__(16) unsigned char Bs[2][128 * BPITCH];   // 18432B

    const int tid  = threadIdx.x;
    const int warp = tid >> 5;
    const int lane = tid & 31;
    const int b    = blockIdx.y >> 3;
    const int h    = blockIdx.y & 7;
    const int rowBase = blockIdx.x * 128;

    const uint32_t ksA = smem_u32(Ks);
    const uint32_t vsA = smem_u32(Vs);
    const uint32_t bsA = smem_u32(Bs);

    auto issue_tile = [&](int t, int s) {
        const int jt = t * 64;
        const char* kb = (const char*)g_Kb + ((size_t)(b * HWP + jt) * DM + h * DK) * 2;
        const char* vb = (const char*)g_Vb + ((size_t)(b * HWP + jt) * DM + h * DK) * 2;
        {
            const int i = tid;  // 256 chunks each for K and V
            const int r = i >> 2, q = i & 3;
            CPA16(ksA + s * 5120 + r * 80 + q * 16, kb + (size_t)r * (DM * 2) + q * 16);
            CPA16(vsA + s * 5120 + r * 80 + q * 16, vb + (size_t)r * (DM * 2) + q * 16);
        }
        const unsigned char* bb = g_biasF8 + (size_t)rowBase * HWP + jt;
        #pragma unroll
        for (int i = tid; i < 1024; i += 256) {
            const int r = i >> 3, q = i & 7;
            CPA8(bsA + s * 9216 + r * BPITCH + q * 8, bb + (size_t)r * HWP + q * 8);
        }
        CPA_COMMIT();
    };

    // Q tile
    {
        const __nv_bfloat16* qsrc = g_Qb + (size_t)(b * HWP + rowBase) * DM + h * DK;
        #pragma unroll
        for (int i = tid; i < 512; i += 256) {
            const int r = i >> 2, q = i & 3;
            *(uint4*)(Qs + r * QPAD + q * 8) = *(const uint4*)(qsrc + (size_t)r * DM + q * 8);
        }
    }
    issue_tile(0, 0);
    __syncthreads();

    // each warp owns 16 query rows: [warp*16, warp*16+16)
    uint32_t qa[2][4];
    {
        const int arow = (lane & 7) + ((lane >> 3) & 1) * 8;
        const int acol = (lane >> 4) * 8;
        #pragma unroll
        for (int ks = 0; ks < 2; ks++) {
            uint32_t a = smem_u32(Qs + (warp * 16 + arow) * QPAD + ks * 16 + acol);
            ldmx4(qa[ks][0], qa[ks][1], qa[ks][2], qa[ks][3], a);
        }
    }

    const int c2 = 2 * (lane & 3);
    int boff[2];
    #pragma unroll
    for (int rr = 0; rr < 2; rr++)
        boff[rr] = (warp * 16 + (lane >> 2) + rr * 8) * BPITCH + c2;

    const float SC2 = QK_SCALE * LOG2E;
    float o[4][4] = {};
    float rsum[2] = {};

    for (int t = 0; t < HWP / 64; t++) {
        CPA_WAIT0();
        __syncthreads();
        if (t < 35) issue_tile(t + 1, (t + 1) & 1);
        const int s = t & 1;

        // --- S = Q K^T ---
        float S[8][4] = {};
        {
            const int brow = (lane & 7) + ((lane >> 4) & 1) * 8;
            const int bcol = ((lane >> 3) & 1) * 8;
            #pragma unroll
            for (int np = 0; np < 4; np++) {
                #pragma unroll
                for (int ks = 0; ks < 2; ks++) {
                    uint32_t kf[4];
                    uint32_t a = smem_u32(&Ks[s][(np * 16 + brow) * QPAD + ks * 16 + bcol]);
                    ldmx4(kf[0], kf[1], kf[2], kf[3], a);
                    mma16816(S[2 * np],     qa[ks], kf);
                    mma16816(S[2 * np + 1], qa[ks], kf + 2);
                }
            }
        }

        // --- P = ex2(S*SC2 + biasF8) ---
        const unsigned char* bbuf = Bs[s];
        uint32_t pa[4][4];
        #pragma unroll
        for (int n = 0; n < 8; n++) {
            float p[4];
            #pragma unroll
            for (int rr = 0; rr < 2; rr++) {
                const unsigned short hs = *(const unsigned short*)(bbuf + boff[rr] + n * 8);
                uint32_t f2;
                asm("cvt.rn.f16x2.e4m3x2 %0, %1;" : "=r"(f2) : "h"(hs));
                float b0, b1;
                asm("{.reg .b16 l,h; mov.b32 {l,h}, %2; cvt.f32.f16 %0, l; cvt.f32.f16 %1, h;}"
                    : "=f"(b0), "=f"(b1) : "r"(f2));
                const float p0 = ex2f(fmaf(S[n][rr * 2 + 0], SC2, b0));
                const float p1 = ex2f(fmaf(S[n][rr * 2 + 1], SC2, b1));
                p[rr * 2 + 0] = p0;
                p[rr * 2 + 1] = p1;
                rsum[rr] += p0 + p1;
            }
            pa[n >> 1][(n & 1) * 2 + 0] = pack_bf16x2(p[0], p[1]);
            pa[n >> 1][(n & 1) * 2 + 1] = pack_bf16x2(p[2], p[3]);
        }

        // --- O += P @ V ---
        {
            const int vrow = (lane & 7) + ((lane >> 3) & 1) * 8;
            const int vcol = ((lane >> 4) & 1) * 8;
            #pragma unroll
            for (int k2 = 0; k2 < 4; k2++) {
                #pragma unroll
                for (int dp = 0; dp < 2; dp++) {
                    uint32_t vf[4];
                    uint32_t a = smem_u32(&Vs[s][(k2 * 16 + vrow) * QPAD + dp * 16 + vcol]);
                    ldmx4t(vf[0], vf[1], vf[2], vf[3], a);
                    mma16816(o[2 * dp],     pa[k2], vf);
                    mma16816(o[2 * dp + 1], pa[k2], vf + 2);
                }
            }
        }
    }

    #pragma unroll
    for (int rr = 0; rr < 2; rr++) {
        float sv = rsum[rr];
        sv += __shfl_xor_sync(0xFFFFFFFF, sv, 1);
        sv += __shfl_xor_sync(0xFFFFFFFF, sv, 2);
        rsum[rr] = 1.0f / sv;
    }

    #pragma unroll
    for (int rr = 0; rr < 2; rr++) {
        const int grow = rowBase + warp * 16 + (lane >> 2) + rr * 8;
        __nv_bfloat16* od = g_Ob + (size_t)(b * HWP + grow) * DM + h * DK;
        const float inv = rsum[rr];
        #pragma unroll
        for (int n = 0; n < 4; n++) {
            *(uint32_t*)(od + n * 8 + c2) =
                pack_bf16x2(o[n][rr * 2 + 0] * inv, o[n][rr * 2 + 1] * inv);
        }
    }
}

// ---------------------------------------------------------------------------
// Kernel 3: HMMA output projection + residual, cp.async double-buffered.
// CTA 256 thr: M=64 c x N=128 p. Grid (36, 4).
// ---------------------------------------------------------------------------
__global__ __launch_bounds__(256) void outproj_mma_kernel(
    const float* __restrict__ x, const float* __restrict__ bo,
    const float* __restrict__ gamma_p, float* __restrict__ out)
{
    __shared__ __align__(16) __nv_bfloat16 ws2[2][64 * QPAD];    // 2 x 5120B
    __shared__ __align__(16) __nv_bfloat16 os2[2][128 * QPAD];   // 2 x 10240B

    const int tid  = threadIdx.x;
    const int warp = tid >> 5;
    const int lane = tid & 31;

    const int gp    = blockIdx.x * 128;
    const int b     = gp / HWP;
    const int pb    = gp - b * HWP;
    const int cBase = blockIdx.y * 64;
    const float gamma = *gamma_p;

    const uint32_t wsA = smem_u32(ws2);
    const uint32_t osA = smem_u32(os2);

    auto load_chunk = [&](int s, int k0) {
        const char* wb = (const char*)g_Wob + ((size_t)cBase * DM + k0) * 2;
        {
            const int i = tid;   // 256 chunks: 64 rows x 4
            const int r = i >> 2, q = i & 3;
            CPA16(wsA + s * 5120 + r * 80 + q * 16, wb + (size_t)r * (DM * 2) + q * 16);
        }
        const char* ob = (const char*)g_Ob + ((size_t)(b * HWP + pb) * DM + k0) * 2;
        #pragma unroll
        for (int i = tid; i < 512; i += 256) {   // 512 chunks: 128 rows x 4
            const int r = i >> 2, q = i & 3;
            CPA16(osA + s * 10240 + r * 80 + q * 16, ob + (size_t)r * (DM * 2) + q * 16);
        }
        CPA_COMMIT();
    };

    const int cw = warp & 1;     // c-group: rows cw*32
    const int pw = warp >> 1;    // p-group: cols pw*32

    float acc[2][4][4] = {};

    load_chunk(0, 0);

    for (int c = 0; c < 8; c++) {
        CPA_WAIT0();
        __syncthreads();
        if (c < 7) load_chunk((c + 1) & 1, (c + 1) * 32);
        const int s = c & 1;

        const int arow = (lane & 7) + ((lane >> 3) & 1) * 8;
        const int acol = (lane >> 4) * 8;
        const int brow = (lane & 7) + ((lane >> 4) & 1) * 8;
        const int bcol = ((lane >> 3) & 1) * 8;

        #pragma unroll
        for (int ks = 0; ks < 2; ks++) {
            uint32_t af[2][4];
            #pragma unroll
            for (int mt = 0; mt < 2; mt++) {
                uint32_t a = smem_u32(&ws2[s][(cw * 32 + mt * 16 + arow) * QPAD + ks * 16 + acol]);
                ldmx4(af[mt][0], af[mt][1], af[mt][2], af[mt][3], a);
            }
            #pragma unroll
            for (int nt = 0; nt < 2; nt++) {
                uint32_t bf[4];
                uint32_t a = smem_u32(&os2[s][(pw * 32 + nt * 16 + brow) * QPAD + ks * 16 + bcol]);
                ldmx4(bf[0], bf[1], bf[2], bf[3], a);
                #pragma unroll
                for (int mt = 0; mt < 2; mt++) {
                    mma16816(acc[mt][2 * nt],     af[mt], bf);
                    mma16816(acc[mt][2 * nt + 1], af[mt], bf + 2);
                }
            }
        }
    }

    const int c2 = 2 * (lane & 3);
    #pragma unroll
    for (int mt = 0; mt < 2; mt++) {
        #pragma unroll
        for (int rr = 0; rr < 2; rr++) {
            const int c = cBase + cw * 32 + mt * 16 + (lane >> 2) + rr * 8;
            const float bias = bo[c];
            #pragma unroll
            for (int n = 0; n < 4; n++) {
                const int p = pb + pw * 32 + n * 8 + c2;
                const size_t idx = (size_t)b * CC * HWP + (size_t)c * HWP + p;
                float2 xv = *(const float2*)(x + idx);
                float2 r;
                r.x = xv.x + gamma * acc[mt][n][rr * 2 + 0] + bias;
                r.y = xv.y + gamma * acc[mt][n][rr * 2 + 1] + bias;
                *(float2*)(out + idx) = r;
            }
        }
    }
}

// ---------------------------------------------------------------------------
extern "C" void kernel_launch(void* const* d_in, const int* in_sizes, int n_in,
                              void* d_out, int out_size)
{
    (void)in_sizes; (void)n_in; (void)out_size;
    const float* x   = (const float*)d_in[0];
    const float* Wq  = (const float*)d_in[1];
    const float* bq  = (const float*)d_in[2];
    const float* Wk  = (const float*)d_in[3];
    const float* bk  = (const float*)d_in[4];
    const float* Wv  = (const float*)d_in[5];
    const float* bv  = (const float*)d_in[6];
    const float* Wo  = (const float*)d_in[7];
    const float* bo  = (const float*)d_in[8];
    const float* lam = (const float*)d_in[9];
    const float* gam = (const float*)d_in[10];
    float* out = (float*)d_out;

    convw_kernel<<<512, 256>>>(Wq, Wk, Wv, Wo);
    xt_kernel<<<dim3(HWP / 64, CC / 64, BB), 256>>>(x);
    bias_kernel<<<HWP * HWP / 512, 256>>>(lam);

    qkv_mma_kernel<<<dim3(BB * HWP / 64, DM / 64), 256>>>(bq, bk, bv);

    attn_mma_kernel<<<dim3(HWP / 128, BB * NH), 256>>>();

    outproj_mma_kernel<<<dim3(BB * HWP / 128, CC / 64), 256>>>(x, bo, gam, out);
}

// round 9
// speedup vs baseline: 6.4866x; 1.1342x over previous
#include <cuda_runtime.h>
#include <cuda_fp16.h>
#include <cstdint>

#define BB 2
#define CC 256
#define HH 48
#define WW 48
#define HWP 2304
#define DM 256
#define NH 8
#define DK 32
#define QK_SCALE 0.17677669529663689f   // 1/sqrt(32)
#define LOG2E 1.4426950408889634f
#define EXP_OFF 7.0f                     // p scaled by 2^-7; cancels in softmax
#define QPAD 40                          // f16 pitch = 80B (16B multiple)
#define WPAD 40
#define BPITCH 80                        // bias tile pitch bytes (16B multiple for cp.async)
#define NSPLIT 2
#define NTILE (HWP / 64)                 // 36
#define TPS (NTILE / NSPLIT)             // 18 tiles per split

// ---------------- scratch (allocation-free) ----------------
__device__ __half g_Qh[BB * HWP * DM];
__device__ __half g_Kh[BB * HWP * DM];
__device__ __half g_Vh[BB * HWP * DM];
__device__ __half g_Oph[NSPLIT * BB * HWP * DM];   // partial attention out
__device__ float  g_rsP[NSPLIT * BB * NH * HWP];   // partial row sums
__device__ __half g_Oh[BB * HWP * DM];             // combined attention out
__device__ __half g_xh[BB * HWP * CC];             // x transposed (b,p,c)
__device__ __half g_Wqh[DM * CC];
__device__ __half g_Wkh[DM * CC];
__device__ __half g_Wvh[DM * CC];
__device__ __half g_Woh[CC * DM];
__device__ unsigned char g_biasF8[HWP * HWP];      // lam*dm*log2e, e4m3

// ---------------- helpers ----------------
__device__ __forceinline__ uint32_t smem_u32(const void* p) {
    uint32_t a;
    asm("{ .reg .u64 t; cvta.to.shared.u64 t, %1; cvt.u32.u64 %0, t; }" : "=r"(a) : "l"(p));
    return a;
}
__device__ __forceinline__ void ldmx4(uint32_t& r0, uint32_t& r1, uint32_t& r2, uint32_t& r3, uint32_t a) {
    asm volatile("ldmatrix.sync.aligned.m8n8.x4.shared.b16 {%0,%1,%2,%3}, [%4];"
                 : "=r"(r0), "=r"(r1), "=r"(r2), "=r"(r3) : "r"(a));
}
__device__ __forceinline__ void ldmx4t(uint32_t& r0, uint32_t& r1, uint32_t& r2, uint32_t& r3, uint32_t a) {
    asm volatile("ldmatrix.sync.aligned.m8n8.x4.trans.shared.b16 {%0,%1,%2,%3}, [%4];"
                 : "=r"(r0), "=r"(r1), "=r"(r2), "=r"(r3) : "r"(a));
}
// f16 inputs, f32 accumulate (projections)
__device__ __forceinline__ void mma16816f(float* c, const uint32_t* a, const uint32_t* b) {
    asm volatile("mma.sync.aligned.m16n8k16.row.col.f32.f16.f16.f32 "
                 "{%0,%1,%2,%3},{%4,%5,%6,%7},{%8,%9},{%0,%1,%2,%3};"
                 : "+f"(c[0]), "+f"(c[1]), "+f"(c[2]), "+f"(c[3])
                 : "r"(a[0]), "r"(a[1]), "r"(a[2]), "r"(a[3]), "r"(b[0]), "r"(b[1]));
}
// f16 inputs, f16 accumulate (attention)
__device__ __forceinline__ void mma16816h(uint32_t* d, const uint32_t* a, uint32_t b0, uint32_t b1) {
    asm volatile("mma.sync.aligned.m16n8k16.row.col.f16.f16.f16.f16 "
                 "{%0,%1},{%2,%3,%4,%5},{%6,%7},{%0,%1};"
                 : "+r"(d[0]), "+r"(d[1])
                 : "r"(a[0]), "r"(a[1]), "r"(a[2]), "r"(a[3]), "r"(b0), "r"(b1));
}
__device__ __forceinline__ uint32_t f2h2(float lo, float hi) {
    __half2 h = __floats2half2_rn(lo, hi);
    return *(uint32_t*)&h;
}
__device__ __forceinline__ uint32_t hfma2u(uint32_t a, uint32_t b, uint32_t c) {
    uint32_t d;
    asm("fma.rn.f16x2 %0, %1, %2, %3;" : "=r"(d) : "r"(a), "r"(b), "r"(c));
    return d;
}
__device__ __forceinline__ uint32_t hadd2u(uint32_t a, uint32_t b) {
    uint32_t d;
    asm("add.rn.f16x2 %0, %1, %2;" : "=r"(d) : "r"(a), "r"(b));
    return d;
}
__device__ __forceinline__ uint32_t hex2u(uint32_t a) {
    uint32_t d;
    asm("ex2.approx.f16x2 %0, %1;" : "=r"(d) : "r"(a));
    return d;
}
__device__ __forceinline__ float2 h2f2(uint32_t u) {
    __half2 h = *(__half2*)&u;
    return __half22float2(h);
}
#define CPA16(dst, src) asm volatile("cp.async.cg.shared.global [%0], [%1], 16;" :: "r"(dst), "l"(src))
#define CPA_COMMIT()    asm volatile("cp.async.commit_group;")
#define CPA_WAIT0()     asm volatile("cp.async.wait_group 0;")
#define CPA_WAIT1()     asm volatile("cp.async.wait_group 1;")

// ---------------------------------------------------------------------------
// Prep 1: convert Wq/Wk/Wv/Wo fp32 -> f16.
// ---------------------------------------------------------------------------
__global__ __launch_bounds__(256) void convw_kernel(
    const float* __restrict__ Wq, const float* __restrict__ Wk,
    const float* __restrict__ Wv, const float* __restrict__ Wo)
{
    const int idx = blockIdx.x * 256 + threadIdx.x;
    const int mat = idx >> 15;
    const int off = idx & 32767;
    const float* s = (mat == 0) ? Wq : ((mat == 1) ? Wk : ((mat == 2) ? Wv : Wo));
    uint32_t* d = (uint32_t*)((mat == 0) ? g_Wqh : ((mat == 1) ? g_Wkh : ((mat == 2) ? g_Wvh : g_Woh)));
    d[off] = f2h2(s[off * 2], s[off * 2 + 1]);
}

// ---------------------------------------------------------------------------
// Prep 2: transpose+convert x (b,c,p) fp32 -> g_xh (b,p,c) f16.
// ---------------------------------------------------------------------------
__global__ __launch_bounds__(256) void xt_kernel(const float* __restrict__ x)
{
    __shared__ float ts[64][65];
    const int b  = blockIdx.z;
    const int pB = blockIdx.x * 64;
    const int cB = blockIdx.y * 64;
    #pragma unroll
    for (int i = threadIdx.x; i < 4096; i += 256) {
        const int c = i >> 6, p = i & 63;
        ts[c][p] = x[((size_t)b * CC + cB + c) * HWP + pB + p];
    }
    __syncthreads();
    #pragma unroll
    for (int i = threadIdx.x; i < 2048; i += 256) {
        const int p = i >> 5, q = i & 31;
        *((uint32_t*)g_xh + ((size_t)(b * HWP + pB + p) * CC + cB) / 2 + q) =
            f2h2(ts[2 * q][p], ts[2 * q + 1][p]);
    }
}

// ---------------------------------------------------------------------------
// Prep 3: bias matrix T[i][j] = lam * exp(-dist(i,j)) * log2e, e4m3 fp8.
// ---------------------------------------------------------------------------
__global__ __launch_bounds__(256) void bias_kernel(const float* __restrict__ lam_p)
{
    const int idx = blockIdx.x * 256 + threadIdx.x;
    const float lam2 = (*lam_p) * LOG2E;
    const int i  = idx / (HWP / 2);
    const int jj = (idx - i * (HWP / 2)) * 2;
    const int yi = i / WW,  xi = i - yi * WW;
    const int yj = jj / WW, xj = jj - yj * WW;
    const int dy  = yi - yj;
    const int dx0 = xi - xj;
    const int dx1 = dx0 - 1;
    const float t0 = lam2 * __expf(-sqrtf((float)(dy * dy + dx0 * dx0)));
    const float t1 = lam2 * __expf(-sqrtf((float)(dy * dy + dx1 * dx1)));
    unsigned short u;
    asm("cvt.rn.satfinite.e4m3x2.f32 %0, %1, %2;" : "=h"(u) : "f"(t1), "f"(t0));
    ((unsigned short*)g_biasF8)[idx] = u;
}

// ---------------------------------------------------------------------------
// Kernel 1: HMMA fused QKV + pe + bias, 3-stage cp.async pipeline.
// CTA 256 thr: M=64 pixels x N=64 dims, all 3 matrices. Grid (72, 4).
// ---------------------------------------------------------------------------
__global__ __launch_bounds__(256) void qkv_mma_kernel(
    const float* __restrict__ bq, const float* __restrict__ bk, const float* __restrict__ bv)
{
    __shared__ __align__(16) __half As[3][64 * QPAD];       // 3 x 5120B
    __shared__ __align__(16) __half Ws[3][3][64 * WPAD];    // 3 x 15360B

    const int tid  = threadIdx.x;
    const int warp = tid >> 5;
    const int lane = tid & 31;

    const int gp    = blockIdx.x * 64;
    const int b     = gp / HWP;
    const int pb    = gp - b * HWP;
    const int dBase = blockIdx.y * 64;
    const bool use_y = (dBase >= 128);

    const uint32_t asA = smem_u32(As);
    const uint32_t wsA = smem_u32(Ws);

    const __half* gW[3] = { g_Wqh, g_Wkh, g_Wvh };

    auto load_chunk = [&](int s, int c0) {
        const char* ab = (const char*)g_xh + ((size_t)(b * HWP + pb) * CC + c0) * 2;
        {
            const int i = tid;  // 256 chunks: 64 rows x 4
            const int r = i >> 2, q = i & 3;
            CPA16(asA + s * 5120 + r * 80 + q * 16, ab + (size_t)r * (CC * 2) + q * 16);
        }
        #pragma unroll
        for (int i = tid; i < 768; i += 256) {
            const int mat = i / 256;
            const int rem = i - mat * 256;
            const int r = rem >> 2, q = rem & 3;
            const char* wb = (const char*)gW[mat] + ((size_t)(dBase + r) * CC + c0) * 2;
            CPA16(wsA + s * 15360 + mat * 5120 + r * 80 + q * 16, wb + q * 16);
        }
        CPA_COMMIT();
    };

    const int mw = warp >> 2;      // rows mw*32
    const int nw = warp & 3;       // dims nw*16

    float acc[3][2][2][4] = {};

    load_chunk(0, 0);
    load_chunk(1, 32);

    for (int c = 0; c < 8; c++) {
        if (c == 7) { CPA_WAIT0(); } else { CPA_WAIT1(); }
        __syncthreads();
        if (c < 6) load_chunk((c + 2) % 3, (c + 2) * 32);

        const int s = c % 3;
        const __half* Ab = As[s];

        const int arow = (lane & 7) + ((lane >> 3) & 1) * 8;
        const int acol = (lane >> 4) * 8;
        const int brow = (lane & 7) + ((lane >> 4) & 1) * 8;
        const int bcol = ((lane >> 3) & 1) * 8;

        #pragma unroll
        for (int ks = 0; ks < 2; ks++) {
            uint32_t af[2][4];
            #pragma unroll
            for (int mt = 0; mt < 2; mt++) {
                uint32_t a = smem_u32(Ab + (mw * 32 + mt * 16 + arow) * QPAD + ks * 16 + acol);
                ldmx4(af[mt][0], af[mt][1], af[mt][2], af[mt][3], a);
            }
            #pragma unroll
            for (int mat = 0; mat < 3; mat++) {
                uint32_t bf[4];
                uint32_t a = smem_u32(&Ws[s][mat][(nw * 16 + brow) * WPAD + ks * 16 + bcol]);
                ldmx4(bf[0], bf[1], bf[2], bf[3], a);
                #pragma unroll
                for (int mt = 0; mt < 2; mt++) {
                    mma16816f(acc[mat][mt][0], af[mt], bf);
                    mma16816f(acc[mat][mt][1], af[mt], bf + 2);
                }
            }
        }
    }

    // pe table (f16) in the now-free A staging region (6144B <= 15360B)
    __syncthreads();
    __half* pes = (__half*)As;   // [coord 0..47][dloc 0..63]
    for (int i = tid; i < 48 * 64; i += 256) {
        const int coord = i >> 6;
        const int dloc  = i & 63;
        const int dl    = (dBase + dloc) - (use_y ? 128 : 0);
        const float freq = __expf(-(float)(dl >> 1) * 0.14391156642875743f);
        const float arg  = (float)coord * freq;
        pes[i] = __float2half((dl & 1) ? __cosf(arg) : __sinf(arg));
    }
    __syncthreads();

    const int c2 = 2 * (lane & 3);
    #pragma unroll
    for (int mt = 0; mt < 2; mt++) {
        #pragma unroll
        for (int rr = 0; rr < 2; rr++) {
            const int ploc = mw * 32 + mt * 16 + (lane >> 2) + rr * 8;
            const int p    = pb + ploc;
            const int coord = use_y ? (p / WW) : (p % WW);
            const size_t rowIdx = ((size_t)b * HWP + p) * DM + dBase;
            #pragma unroll
            for (int nt = 0; nt < 2; nt++) {
                const int dloc = nw * 16 + nt * 8 + c2;
                const int d    = dBase + dloc;
                const float pe0 = __half2float(pes[coord * 64 + dloc]);
                const float pe1 = __half2float(pes[coord * 64 + dloc + 1]);
                const float q0 = acc[0][mt][nt][rr * 2 + 0] + bq[d]     + pe0;
                const float q1 = acc[0][mt][nt][rr * 2 + 1] + bq[d + 1] + pe1;
                const float k0 = acc[1][mt][nt][rr * 2 + 0] + bk[d]     + pe0;
                const float k1 = acc[1][mt][nt][rr * 2 + 1] + bk[d + 1] + pe1;
                const float v0 = acc[2][mt][nt][rr * 2 + 0] + bv[d];
                const float v1 = acc[2][mt][nt][rr * 2 + 1] + bv[d + 1];
                *(uint32_t*)(g_Qh + rowIdx + dloc) = f2h2(q0, q1);
                *(uint32_t*)(g_Kh + rowIdx + dloc) = f2h2(k0, k1);
                *(uint32_t*)(g_Vh + rowIdx + dloc) = f2h2(v0, v1);
            }
        }
    }
}

// ---------------------------------------------------------------------------
// Kernel 2: f16 HMMA flash attention, KV-split across z. CTA 128 thr (4 warps,
// 32 rows each). Grid (18, 16, NSPLIT). f16-accumulate + half2 epilogue.
// ---------------------------------------------------------------------------
__global__ __launch_bounds__(128, 4) void attn_mma_kernel()
{
    __shared__ __align__(16) __half Qs[128 * QPAD];          // 10240B
    __shared__ __align__(16) __half Ks[2][64 * QPAD];        // 10240B
    __shared__ __align__(16) __half Vs[2][64 * QPAD];        // 10240B
    __shared__ __align__(16) unsigned char Bs[2][128 * BPITCH]; // 20480B

    const int tid  = threadIdx.x;
    const int warp = tid >> 5;
    const int lane = tid & 31;
    const int b    = blockIdx.y >> 3;
    const int h    = blockIdx.y & 7;
    const int rowBase = blockIdx.x * 128;
    const int z    = blockIdx.z;
    const int tBeg = z * TPS;

    const uint32_t ksA = smem_u32(Ks);
    const uint32_t vsA = smem_u32(Vs);
    const uint32_t bsA = smem_u32(Bs);

    auto issue_tile = [&](int t, int s) {
        const int jt = t * 64;
        const char* kb = (const char*)g_Kh + ((size_t)(b * HWP + jt) * DM + h * DK) * 2;
        const char* vb = (const char*)g_Vh + ((size_t)(b * HWP + jt) * DM + h * DK) * 2;
        #pragma unroll
        for (int i = tid; i < 256; i += 128) {
            const int r = i >> 2, q = i & 3;
            CPA16(ksA + s * 5120 + r * 80 + q * 16, kb + (size_t)r * (DM * 2) + q * 16);
            CPA16(vsA + s * 5120 + r * 80 + q * 16, vb + (size_t)r * (DM * 2) + q * 16);
        }
        const unsigned char* bb = g_biasF8 + (size_t)rowBase * HWP + jt;
        #pragma unroll
        for (int i = tid; i < 512; i += 128) {
            const int r = i >> 2, q = i & 3;
            CPA16(bsA + s * 10240 + r * BPITCH + q * 16, bb + (size_t)r * HWP + q * 16);
        }
        CPA_COMMIT();
    };

    // Q tile
    {
        const __half* qsrc = g_Qh + (size_t)(b * HWP + rowBase) * DM + h * DK;
        #pragma unroll
        for (int i = tid; i < 512; i += 128) {
            const int r = i >> 2, q = i & 3;
            *(uint4*)(Qs + r * QPAD + q * 8) = *(const uint4*)(qsrc + (size_t)r * DM + q * 8);
        }
    }
    issue_tile(tBeg, 0);
    __syncthreads();

    uint32_t qa[2][2][4];   // [mtile][kstep][4]
    {
        const int arow = (lane & 7) + ((lane >> 3) & 1) * 8;
        const int acol = (lane >> 4) * 8;
        #pragma unroll
        for (int m = 0; m < 2; m++)
            #pragma unroll
            for (int ks = 0; ks < 2; ks++) {
                uint32_t a = smem_u32(Qs + (warp * 32 + m * 16 + arow) * QPAD + ks * 16 + acol);
                ldmx4(qa[m][ks][0], qa[m][ks][1], qa[m][ks][2], qa[m][ks][3], a);
            }
    }

    const int c2 = 2 * (lane & 3);
    int boff[2][2];
    #pragma unroll
    for (int m = 0; m < 2; m++)
        #pragma unroll
        for (int rr = 0; rr < 2; rr++)
            boff[m][rr] = (warp * 32 + m * 16 + (lane >> 2) + rr * 8) * BPITCH + c2;

    const uint32_t SC2h = f2h2(QK_SCALE * LOG2E, QK_SCALE * LOG2E);
    const uint32_t NEGO = f2h2(-EXP_OFF, -EXP_OFF);

    uint32_t o[2][4][2];      // f16x2 accumulators [m][n8][rr-pair regs]
    uint32_t rsum2[2][2];     // f16x2 partial row sums [m][rr]
    #pragma unroll
    for (int m = 0; m < 2; m++) {
        #pragma unroll
        for (int n = 0; n < 4; n++) { o[m][n][0] = 0u; o[m][n][1] = 0u; }
        rsum2[m][0] = 0u; rsum2[m][1] = 0u;
    }

    for (int t = 0; t < TPS; t++) {
        CPA_WAIT0();
        __syncthreads();
        if (t < TPS - 1) issue_tile(tBeg + t + 1, (t + 1) & 1);
        const int s = t & 1;

        // --- S = Q K^T (f16 accumulate) ---
        uint32_t S[2][8][2];
        #pragma unroll
        for (int m = 0; m < 2; m++)
            #pragma unroll
            for (int n = 0; n < 8; n++) { S[m][n][0] = 0u; S[m][n][1] = 0u; }
        {
            const int brow = (lane & 7) + ((lane >> 4) & 1) * 8;
            const int bcol = ((lane >> 3) & 1) * 8;
            #pragma unroll
            for (int np = 0; np < 4; np++) {
                #pragma unroll
                for (int ks = 0; ks < 2; ks++) {
                    uint32_t kf[4];
                    uint32_t a = smem_u32(&Ks[s][(np * 16 + brow) * QPAD + ks * 16 + bcol]);
                    ldmx4(kf[0], kf[1], kf[2], kf[3], a);
                    #pragma unroll
                    for (int m = 0; m < 2; m++) {
                        mma16816h(S[m][2 * np],     qa[m][ks], kf[0], kf[1]);
                        mma16816h(S[m][2 * np + 1], qa[m][ks], kf[2], kf[3]);
                    }
                }
            }
        }

        // --- in-place half2 epilogue: P = 2^(S*c + bias - OFF) ---
        const unsigned char* bbuf = Bs[s];
        #pragma unroll
        for (int n = 0; n < 8; n++) {
            #pragma unroll
            for (int m = 0; m < 2; m++) {
                const unsigned short h0 = *(const unsigned short*)(bbuf + boff[m][0] + n * 8);
                const unsigned short h1 = *(const unsigned short*)(bbuf + boff[m][1] + n * 8);
                uint32_t b0, b1;
                asm("cvt.rn.f16x2.e4m3x2 %0, %1;" : "=r"(b0) : "h"(h0));
                asm("cvt.rn.f16x2.e4m3x2 %0, %1;" : "=r"(b1) : "h"(h1));
                b0 = hadd2u(b0, NEGO);
                b1 = hadd2u(b1, NEGO);
                S[m][n][0] = hex2u(hfma2u(S[m][n][0], SC2h, b0));
                S[m][n][1] = hex2u(hfma2u(S[m][n][1], SC2h, b1));
                rsum2[m][0] = hadd2u(rsum2[m][0], S[m][n][0]);
                rsum2[m][1] = hadd2u(rsum2[m][1], S[m][n][1]);
            }
        }

        // --- O += P @ V (f16 accumulate); S regs are the A-fragments ---
        {
            const int vrow = (lane & 7) + ((lane >> 3) & 1) * 8;
            const int vcol = ((lane >> 4) & 1) * 8;
            #pragma unroll
            for (int k2 = 0; k2 < 4; k2++) {
                #pragma unroll
                for (int dp = 0; dp < 2; dp++) {
                    uint32_t vf[4];
                    uint32_t a = smem_u32(&Vs[s][(k2 * 16 + vrow) * QPAD + dp * 16 + vcol]);
                    ldmx4t(vf[0], vf[1], vf[2], vf[3], a);
                    #pragma unroll
                    for (int m = 0; m < 2; m++) {
                        mma16816h(o[m][2 * dp],     &S[m][2 * k2][0], vf[0], vf[1]);
                        mma16816h(o[m][2 * dp + 1], &S[m][2 * k2][0], vf[2], vf[3]);
                    }
                }
            }
        }
    }

    // partial row sums -> gmem (fold half2, reduce over quad)
    #pragma unroll
    for (int m = 0; m < 2; m++)
        #pragma unroll
        for (int rr = 0; rr < 2; rr++) {
            float2 f = h2f2(rsum2[m][rr]);
            float sv = f.x + f.y;
            sv += __shfl_xor_sync(0xFFFFFFFF, sv, 1);
            sv += __shfl_xor_sync(0xFFFFFFFF, sv, 2);
            if ((lane & 3) == 0) {
                const int grow = rowBase + warp * 32 + m * 16 + (lane >> 2) + rr * 8;
                g_rsP[(size_t)z * (BB * NH * HWP) + (size_t)(b * NH + h) * HWP + grow] = sv;
            }
        }

    // partial O (unnormalized, f16) -> gmem
    #pragma unroll
    for (int m = 0; m < 2; m++)
        #pragma unroll
        for (int rr = 0; rr < 2; rr++) {
            const int grow = rowBase + warp * 32 + m * 16 + (lane >> 2) + rr * 8;
            __half* od = g_Oph + (size_t)z * (BB * HWP * DM) + (size_t)(b * HWP + grow) * DM + h * DK;
            #pragma unroll
            for (int n = 0; n < 4; n++)
                *(uint32_t*)(od + n * 8 + c2) = o[m][n][rr];
        }
}

// ---------------------------------------------------------------------------
// Kernel 2b: combine KV-split partials: O = (o0+o1) / (r0+r1).
// ---------------------------------------------------------------------------
__global__ __launch_bounds__(256) void comb_kernel()
{
    const int idx = blockIdx.x * 256 + threadIdx.x;   // BB*HWP*DM/2 u32s
    const int d    = (idx * 2) & (DM - 1);
    const int pidx = (idx * 2) >> 8;                   // (b*HWP + p)
    const int bb   = pidx / HWP;
    const int p    = pidx - bb * HWP;
    const int hh   = d >> 5;
    const size_t rsi = (size_t)(bb * NH + hh) * HWP + p;
    const float r = g_rsP[rsi] + g_rsP[(size_t)(BB * NH * HWP) + rsi];
    const float inv = __fdividef(1.0f, r);
    const uint32_t o0 = ((const uint32_t*)g_Oph)[idx];
    const uint32_t o1 = ((const uint32_t*)g_Oph)[idx + (BB * HWP * DM) / 2];
    float2 f0 = h2f2(o0), f1 = h2f2(o1);
    ((uint32_t*)g_Oh)[idx] = f2h2((f0.x + f1.x) * inv, (f0.y + f1.y) * inv);
}

// ---------------------------------------------------------------------------
// Kernel 3: HMMA output projection + residual, cp.async double-buffered.
// ---------------------------------------------------------------------------
__global__ __launch_bounds__(256) void outproj_mma_kernel(
    const float* __restrict__ x, const float* __restrict__ bo,
    const float* __restrict__ gamma_p, float* __restrict__ out)
{
    __shared__ __align__(16) __half ws2[2][64 * QPAD];    // 2 x 5120B
    __shared__ __align__(16) __half os2[2][128 * QPAD];   // 2 x 10240B

    const int tid  = threadIdx.x;
    const int warp = tid >> 5;
    const int lane = tid & 31;

    const int gp    = blockIdx.x * 128;
    const int b     = gp / HWP;
    const int pb    = gp - b * HWP;
    const int cBase = blockIdx.y * 64;
    const float gamma = *gamma_p;

    const uint32_t wsA = smem_u32(ws2);
    const uint32_t osA = smem_u32(os2);

    auto load_chunk = [&](int s, int k0) {
        const char* wb = (const char*)g_Woh + ((size_t)cBase * DM + k0) * 2;
        {
            const int i = tid;
            const int r = i >> 2, q = i & 3;
            CPA16(wsA + s * 5120 + r * 80 + q * 16, wb + (size_t)r * (DM * 2) + q * 16);
        }
        const char* ob = (const char*)g_Oh + ((size_t)(b * HWP + pb) * DM + k0) * 2;
        #pragma unroll
        for (int i = tid; i < 512; i += 256) {
            const int r = i >> 2, q = i & 3;
            CPA16(osA + s * 10240 + r * 80 + q * 16, ob + (size_t)r * (DM * 2) + q * 16);
        }
        CPA_COMMIT();
    };

    const int cw = warp & 1;
    const int pw = warp >> 1;

    float acc[2][4][4] = {};

    load_chunk(0, 0);

    for (int c = 0; c < 8; c++) {
        CPA_WAIT0();
        __syncthreads();
        if (c < 7) load_chunk((c + 1) & 1, (c + 1) * 32);
        const int s = c & 1;

        const int arow = (lane & 7) + ((lane >> 3) & 1) * 8;
        const int acol = (lane >> 4) * 8;
        const int brow = (lane & 7) + ((lane >> 4) & 1) * 8;
        const int bcol = ((lane >> 3) & 1) * 8;

        #pragma unroll
        for (int ks = 0; ks < 2; ks++) {
            uint32_t af[2][4];
            #pragma unroll
            for (int mt = 0; mt < 2; mt++) {
                uint32_t a = smem_u32(&ws2[s][(cw * 32 + mt * 16 + arow) * QPAD + ks * 16 + acol]);
                ldmx4(af[mt][0], af[mt][1], af[mt][2], af[mt][3], a);
            }
            #pragma unroll
            for (int nt = 0; nt < 2; nt++) {
                uint32_t bf[4];
                uint32_t a = smem_u32(&os2[s][(pw * 32 + nt * 16 + brow) * QPAD + ks * 16 + bcol]);
                ldmx4(bf[0], bf[1], bf[2], bf[3], a);
                #pragma unroll
                for (int mt = 0; mt < 2; mt++) {
                    mma16816f(acc[mt][2 * nt],     af[mt], bf);
                    mma16816f(acc[mt][2 * nt + 1], af[mt], bf + 2);
                }
            }
        }
    }

    const int c2 = 2 * (lane & 3);
    #pragma unroll
    for (int mt = 0; mt < 2; mt++) {
        #pragma unroll
        for (int rr = 0; rr < 2; rr++) {
            const int c = cBase + cw * 32 + mt * 16 + (lane >> 2) + rr * 8;
            const float bias = bo[c];
            #pragma unroll
            for (int n = 0; n < 4; n++) {
                const int p = pb + pw * 32 + n * 8 + c2;
                const size_t idx = (size_t)b * CC * HWP + (size_t)c * HWP + p;
                float2 xv = *(const float2*)(x + idx);
                float2 r;
                r.x = xv.x + gamma * acc[mt][n][rr * 2 + 0] + bias;
                r.y = xv.y + gamma * acc[mt][n][rr * 2 + 1] + bias;
                *(float2*)(out + idx) = r;
            }
        }
    }
}

// ---------------------------------------------------------------------------
extern "C" void kernel_launch(void* const* d_in, const int* in_sizes, int n_in,
                              void* d_out, int out_size)
{
    (void)in_sizes; (void)n_in; (void)out_size;
    const float* x   = (const float*)d_in[0];
    const float* Wq  = (const float*)d_in[1];
    const float* bq  = (const float*)d_in[2];
    const float* Wk  = (const float*)d_in[3];
    const float* bk  = (const float*)d_in[4];
    const float* Wv  = (const float*)d_in[5];
    const float* bv  = (const float*)d_in[6];
    const float* Wo  = (const float*)d_in[7];
    const float* bo  = (const float*)d_in[8];
    const float* lam = (const float*)d_in[9];
    const float* gam = (const float*)d_in[10];
    float* out = (float*)d_out;

    convw_kernel<<<512, 256>>>(Wq, Wk, Wv, Wo);
    xt_kernel<<<dim3(HWP / 64, CC / 64, BB), 256>>>(x);
    bias_kernel<<<HWP * HWP / 512, 256>>>(lam);

    qkv_mma_kernel<<<dim3(BB * HWP / 64, DM / 64), 256>>>(bq, bk, bv);

    attn_mma_kernel<<<dim3(HWP / 128, BB * NH, NSPLIT), 128>>>();
    comb_kernel<<<(BB * HWP * DM / 2) / 256, 256>>>();

    outproj_mma_kernel<<<dim3(BB * HWP / 128, CC / 64), 256>>>(x, bo, gam, out);
}

// round 10
// speedup vs baseline: 6.5748x; 1.0136x over previous
#include <cuda_runtime.h>
#include <cuda_fp16.h>
#include <cstdint>

#define BB 2
#define CC 256
#define HH 48
#define WW 48
#define HWP 2304
#define DM 256
#define NH 8
#define DK 32
#define QK_SCALE 0.17677669529663689f   // 1/sqrt(32)
#define LOG2E 1.4426950408889634f
#define EXP_OFF 7.0f                     // p scaled by 2^-7; cancels in softmax
#define QPAD 40                          // f16 pitch = 80B (16B multiple)
#define WPAD 40
#define BPITCH 80                        // bias tile pitch bytes (16B multiple for cp.async)
#define NSPLIT 2
#define NTILE (HWP / 64)                 // 36
#define TPS (NTILE / NSPLIT)             // 18 tiles per split

// ---------------- scratch (allocation-free) ----------------
__device__ __half g_Qh[BB * HWP * DM];
__device__ __half g_Kh[BB * HWP * DM];
__device__ __half g_Vh[BB * HWP * DM];
__device__ __half g_Oph[NSPLIT * BB * HWP * DM];   // partial attention out
__device__ float  g_rsP[NSPLIT * BB * NH * HWP];   // partial row sums
__device__ __half g_Oh[BB * HWP * DM];             // combined attention out
__device__ __half g_xh[BB * HWP * CC];             // x transposed (b,p,c)
__device__ __half g_Wqh[DM * CC];
__device__ __half g_Wkh[DM * CC];
__device__ __half g_Wvh[DM * CC];
__device__ __half g_Woh[CC * DM];
__device__ unsigned char g_dtab[95 * 95];          // e4m3(lam*exp(-d)*log2e) per (dy,dx)
__device__ unsigned char g_biasF8[HWP * HWP];      // expanded bias matrix

// ---------------- helpers ----------------
__device__ __forceinline__ uint32_t smem_u32(const void* p) {
    uint32_t a;
    asm("{ .reg .u64 t; cvta.to.shared.u64 t, %1; cvt.u32.u64 %0, t; }" : "=r"(a) : "l"(p));
    return a;
}
__device__ __forceinline__ void ldmx4(uint32_t& r0, uint32_t& r1, uint32_t& r2, uint32_t& r3, uint32_t a) {
    asm volatile("ldmatrix.sync.aligned.m8n8.x4.shared.b16 {%0,%1,%2,%3}, [%4];"
                 : "=r"(r0), "=r"(r1), "=r"(r2), "=r"(r3) : "r"(a));
}
__device__ __forceinline__ void ldmx4t(uint32_t& r0, uint32_t& r1, uint32_t& r2, uint32_t& r3, uint32_t a) {
    asm volatile("ldmatrix.sync.aligned.m8n8.x4.trans.shared.b16 {%0,%1,%2,%3}, [%4];"
                 : "=r"(r0), "=r"(r1), "=r"(r2), "=r"(r3) : "r"(a));
}
__device__ __forceinline__ void mma16816f(float* c, const uint32_t* a, const uint32_t* b) {
    asm volatile("mma.sync.aligned.m16n8k16.row.col.f32.f16.f16.f32 "
                 "{%0,%1,%2,%3},{%4,%5,%6,%7},{%8,%9},{%0,%1,%2,%3};"
                 : "+f"(c[0]), "+f"(c[1]), "+f"(c[2]), "+f"(c[3])
                 : "r"(a[0]), "r"(a[1]), "r"(a[2]), "r"(a[3]), "r"(b[0]), "r"(b[1]));
}
__device__ __forceinline__ void mma16816h(uint32_t* d, const uint32_t* a, uint32_t b0, uint32_t b1) {
    asm volatile("mma.sync.aligned.m16n8k16.row.col.f16.f16.f16.f16 "
                 "{%0,%1},{%2,%3,%4,%5},{%6,%7},{%0,%1};"
                 : "+r"(d[0]), "+r"(d[1])
                 : "r"(a[0]), "r"(a[1]), "r"(a[2]), "r"(a[3]), "r"(b0), "r"(b1));
}
__device__ __forceinline__ uint32_t f2h2(float lo, float hi) {
    __half2 h = __floats2half2_rn(lo, hi);
    return *(uint32_t*)&h;
}
__device__ __forceinline__ uint32_t hfma2u(uint32_t a, uint32_t b, uint32_t c) {
    uint32_t d;
    asm("fma.rn.f16x2 %0, %1, %2, %3;" : "=r"(d) : "r"(a), "r"(b), "r"(c));
    return d;
}
__device__ __forceinline__ uint32_t hadd2u(uint32_t a, uint32_t b) {
    uint32_t d;
    asm("add.rn.f16x2 %0, %1, %2;" : "=r"(d) : "r"(a), "r"(b));
    return d;
}
__device__ __forceinline__ uint32_t hex2u(uint32_t a) {
    uint32_t d;
    asm("ex2.approx.f16x2 %0, %1;" : "=r"(d) : "r"(a));
    return d;
}
__device__ __forceinline__ float2 h2f2(uint32_t u) {
    __half2 h = *(__half2*)&u;
    return __half22float2(h);
}
#define CPA16(dst, src) asm volatile("cp.async.cg.shared.global [%0], [%1], 16;" :: "r"(dst), "l"(src))
#define CPA_COMMIT()    asm volatile("cp.async.commit_group;")
#define CPA_WAIT0()     asm volatile("cp.async.wait_group 0;")

// ---------------------------------------------------------------------------
// Prep 0a: distance table (95x95 distinct (dy,dx) values) -> e4m3 bytes.
// ---------------------------------------------------------------------------
__global__ __launch_bounds__(256) void dtab_kernel(const float* __restrict__ lam_p)
{
    const int idx = blockIdx.x * 256 + threadIdx.x;
    if (idx >= 95 * 95) return;
    const float lam2 = (*lam_p) * LOG2E;
    const int dy = idx / 95 - 47;
    const int dx = idx % 95 - 47;
    const float t = lam2 * __expf(-sqrtf((float)(dy * dy + dx * dx)));
    unsigned short u;
    asm("cvt.rn.satfinite.e4m3x2.f32 %0, %1, %2;" : "=h"(u) : "f"(t), "f"(t));
    g_dtab[idx] = (unsigned char)(u & 0xFF);
}

// ---------------------------------------------------------------------------
// Prep 0b: expand bias matrix by table lookup (bandwidth-bound gather).
// One thread per 4 adjacent columns.
// ---------------------------------------------------------------------------
__global__ __launch_bounds__(256) void bias_fill_kernel()
{
    const int idx = blockIdx.x * 256 + threadIdx.x;   // HWP*HWP/4
    const int i  = idx / (HWP / 4);
    const int j0 = (idx - i * (HWP / 4)) * 4;
    const int yi = i / WW, xi = i - yi * WW;
    uint32_t out = 0;
    #pragma unroll
    for (int u = 0; u < 4; u++) {
        const int j  = j0 + u;
        const int yj = j / WW;
        const int xj = j - yj * WW;
        const int ti = (yi - yj + 47) * 95 + (xi - xj + 47);
        out |= (uint32_t)g_dtab[ti] << (u * 8);
    }
    ((uint32_t*)g_biasF8)[idx] = out;
}

// ---------------------------------------------------------------------------
// Prep 1: convert Wq/Wk/Wv/Wo fp32 -> f16.
// ---------------------------------------------------------------------------
__global__ __launch_bounds__(256) void convw_kernel(
    const float* __restrict__ Wq, const float* __restrict__ Wk,
    const float* __restrict__ Wv, const float* __restrict__ Wo)
{
    const int idx = blockIdx.x * 256 + threadIdx.x;
    const int mat = idx >> 15;
    const int off = idx & 32767;
    const float* s = (mat == 0) ? Wq : ((mat == 1) ? Wk : ((mat == 2) ? Wv : Wo));
    uint32_t* d = (uint32_t*)((mat == 0) ? g_Wqh : ((mat == 1) ? g_Wkh : ((mat == 2) ? g_Wvh : g_Woh)));
    d[off] = f2h2(s[off * 2], s[off * 2 + 1]);
}

// ---------------------------------------------------------------------------
// Prep 2: transpose+convert x (b,c,p) fp32 -> g_xh (b,p,c) f16.
// ---------------------------------------------------------------------------
__global__ __launch_bounds__(256) void xt_kernel(const float* __restrict__ x)
{
    __shared__ float ts[64][65];
    const int b  = blockIdx.z;
    const int pB = blockIdx.x * 64;
    const int cB = blockIdx.y * 64;
    #pragma unroll
    for (int i = threadIdx.x; i < 4096; i += 256) {
        const int c = i >> 6, p = i & 63;
        ts[c][p] = x[((size_t)b * CC + cB + c) * HWP + pB + p];
    }
    __syncthreads();
    #pragma unroll
    for (int i = threadIdx.x; i < 2048; i += 256) {
        const int p = i >> 5, q = i & 31;
        *((uint32_t*)g_xh + ((size_t)(b * HWP + pB + p) * CC + cB) / 2 + q) =
            f2h2(ts[2 * q][p], ts[2 * q + 1][p]);
    }
}

// ---------------------------------------------------------------------------
// Kernel 1: HMMA fused QKV + pe + bias, 2-stage cp.async pipeline (R8 shape).
// CTA 256 thr: M=64 pixels x N=64 dims, all 3 matrices. Grid (72, 4).
// ---------------------------------------------------------------------------
__global__ __launch_bounds__(256) void qkv_mma_kernel(
    const float* __restrict__ bq, const float* __restrict__ bk, const float* __restrict__ bv)
{
    __shared__ __align__(16) __half As[2][64 * QPAD];       // 2 x 5120B
    __shared__ __align__(16) __half Ws[2][3][64 * WPAD];    // 2 x 15360B

    const int tid  = threadIdx.x;
    const int warp = tid >> 5;
    const int lane = tid & 31;

    const int gp    = blockIdx.x * 64;
    const int b     = gp / HWP;
    const int pb    = gp - b * HWP;
    const int dBase = blockIdx.y * 64;
    const bool use_y = (dBase >= 128);

    const uint32_t asA = smem_u32(As);
    const uint32_t wsA = smem_u32(Ws);

    const __half* gW[3] = { g_Wqh, g_Wkh, g_Wvh };

    auto load_chunk = [&](int s, int c0) {
        const char* ab = (const char*)g_xh + ((size_t)(b * HWP + pb) * CC + c0) * 2;
        {
            const int i = tid;  // 256 chunks: 64 rows x 4
            const int r = i >> 2, q = i & 3;
            CPA16(asA + s * 5120 + r * 80 + q * 16, ab + (size_t)r * (CC * 2) + q * 16);
        }
        #pragma unroll
        for (int i = tid; i < 768; i += 256) {
            const int mat = i / 256;
            const int rem = i - mat * 256;
            const int r = rem >> 2, q = rem & 3;
            const char* wb = (const char*)gW[mat] + ((size_t)(dBase + r) * CC + c0) * 2;
            CPA16(wsA + s * 15360 + mat * 5120 + r * 80 + q * 16, wb + q * 16);
        }
        CPA_COMMIT();
    };

    const int mw = warp >> 2;      // rows mw*32
    const int nw = warp & 3;       // dims nw*16

    float acc[3][2][2][4] = {};

    load_chunk(0, 0);

    for (int c = 0; c < 8; c++) {
        CPA_WAIT0();
        __syncthreads();
        if (c < 7) load_chunk((c + 1) & 1, (c + 1) * 32);

        const int s = c & 1;
        const __half* Ab = As[s];

        const int arow = (lane & 7) + ((lane >> 3) & 1) * 8;
        const int acol = (lane >> 4) * 8;
        const int brow = (lane & 7) + ((lane >> 4) & 1) * 8;
        const int bcol = ((lane >> 3) & 1) * 8;

        #pragma unroll
        for (int ks = 0; ks < 2; ks++) {
            uint32_t af[2][4];
            #pragma unroll
            for (int mt = 0; mt < 2; mt++) {
                uint32_t a = smem_u32(Ab + (mw * 32 + mt * 16 + arow) * QPAD + ks * 16 + acol);
                ldmx4(af[mt][0], af[mt][1], af[mt][2], af[mt][3], a);
            }
            #pragma unroll
            for (int mat = 0; mat < 3; mat++) {
                uint32_t bf[4];
                uint32_t a = smem_u32(&Ws[s][mat][(nw * 16 + brow) * WPAD + ks * 16 + bcol]);
                ldmx4(bf[0], bf[1], bf[2], bf[3], a);
                #pragma unroll
                for (int mt = 0; mt < 2; mt++) {
                    mma16816f(acc[mat][mt][0], af[mt], bf);
                    mma16816f(acc[mat][mt][1], af[mt], bf + 2);
                }
            }
        }
    }

    // pe table (f16) in the now-free A staging region (6144B <= 10240B)
    __syncthreads();
    __half* pes = (__half*)As;   // [coord 0..47][dloc 0..63]
    for (int i = tid; i < 48 * 64; i += 256) {
        const int coord = i >> 6;
        const int dloc  = i & 63;
        const int dl    = (dBase + dloc) - (use_y ? 128 : 0);
        const float freq = __expf(-(float)(dl >> 1) * 0.14391156642875743f);
        const float arg  = (float)coord * freq;
        pes[i] = __float2half((dl & 1) ? __cosf(arg) : __sinf(arg));
    }
    __syncthreads();

    const int c2 = 2 * (lane & 3);
    #pragma unroll
    for (int mt = 0; mt < 2; mt++) {
        #pragma unroll
        for (int rr = 0; rr < 2; rr++) {
            const int ploc = mw * 32 + mt * 16 + (lane >> 2) + rr * 8;
            const int p    = pb + ploc;
            const int coord = use_y ? (p / WW) : (p % WW);
            const size_t rowIdx = ((size_t)b * HWP + p) * DM + dBase;
            #pragma unroll
            for (int nt = 0; nt < 2; nt++) {
                const int dloc = nw * 16 + nt * 8 + c2;
                const int d    = dBase + dloc;
                const float pe0 = __half2float(pes[coord * 64 + dloc]);
                const float pe1 = __half2float(pes[coord * 64 + dloc + 1]);
                const float q0 = acc[0][mt][nt][rr * 2 + 0] + bq[d]     + pe0;
                const float q1 = acc[0][mt][nt][rr * 2 + 1] + bq[d + 1] + pe1;
                const float k0 = acc[1][mt][nt][rr * 2 + 0] + bk[d]     + pe0;
                const float k1 = acc[1][mt][nt][rr * 2 + 1] + bk[d + 1] + pe1;
                const float v0 = acc[2][mt][nt][rr * 2 + 0] + bv[d];
                const float v1 = acc[2][mt][nt][rr * 2 + 1] + bv[d + 1];
                *(uint32_t*)(g_Qh + rowIdx + dloc) = f2h2(q0, q1);
                *(uint32_t*)(g_Kh + rowIdx + dloc) = f2h2(k0, k1);
                *(uint32_t*)(g_Vh + rowIdx + dloc) = f2h2(v0, v1);
            }
        }
    }
}

// ---------------------------------------------------------------------------
// Kernel 2: f16 HMMA flash attention, KV-split across z. CTA 128 thr (4 warps,
// 32 rows each). Grid (18, 16, NSPLIT). f16-accumulate + half2 epilogue.
// ---------------------------------------------------------------------------
__global__ __launch_bounds__(128, 4) void attn_mma_kernel()
{
    __shared__ __align__(16) __half Qs[128 * QPAD];          // 10240B
    __shared__ __align__(16) __half Ks[2][64 * QPAD];        // 10240B
    __shared__ __align__(16) __half Vs[2][64 * QPAD];        // 10240B
    __shared__ __align__(16) unsigned char Bs[2][128 * BPITCH]; // 20480B

    const int tid  = threadIdx.x;
    const int warp = tid >> 5;
    const int lane = tid & 31;
    const int b    = blockIdx.y >> 3;
    const int h    = blockIdx.y & 7;
    const int rowBase = blockIdx.x * 128;
    const int z    = blockIdx.z;
    const int tBeg = z * TPS;

    const uint32_t ksA = smem_u32(Ks);
    const uint32_t vsA = smem_u32(Vs);
    const uint32_t bsA = smem_u32(Bs);

    auto issue_tile = [&](int t, int s) {
        const int jt = t * 64;
        const char* kb = (const char*)g_Kh + ((size_t)(b * HWP + jt) * DM + h * DK) * 2;
        const char* vb = (const char*)g_Vh + ((size_t)(b * HWP + jt) * DM + h * DK) * 2;
        #pragma unroll
        for (int i = tid; i < 256; i += 128) {
            const int r = i >> 2, q = i & 3;
            CPA16(ksA + s * 5120 + r * 80 + q * 16, kb + (size_t)r * (DM * 2) + q * 16);
            CPA16(vsA + s * 5120 + r * 80 + q * 16, vb + (size_t)r * (DM * 2) + q * 16);
        }
        const unsigned char* bb = g_biasF8 + (size_t)rowBase * HWP + jt;
        #pragma unroll
        for (int i = tid; i < 512; i += 128) {
            const int r = i >> 2, q = i & 3;
            CPA16(bsA + s * 10240 + r * BPITCH + q * 16, bb + (size_t)r * HWP + q * 16);
        }
        CPA_COMMIT();
    };

    // Q tile
    {
        const __half* qsrc = g_Qh + (size_t)(b * HWP + rowBase) * DM + h * DK;
        #pragma unroll
        for (int i = tid; i < 512; i += 128) {
            const int r = i >> 2, q = i & 3;
            *(uint4*)(Qs + r * QPAD + q * 8) = *(const uint4*)(qsrc + (size_t)r * DM + q * 8);
        }
    }
    issue_tile(tBeg, 0);
    __syncthreads();

    uint32_t qa[2][2][4];   // [mtile][kstep][4]
    {
        const int arow = (lane & 7) + ((lane >> 3) & 1) * 8;
        const int acol = (lane >> 4) * 8;
        #pragma unroll
        for (int m = 0; m < 2; m++)
            #pragma unroll
            for (int ks = 0; ks < 2; ks++) {
                uint32_t a = smem_u32(Qs + (warp * 32 + m * 16 + arow) * QPAD + ks * 16 + acol);
                ldmx4(qa[m][ks][0], qa[m][ks][1], qa[m][ks][2], qa[m][ks][3], a);
            }
    }

    const int c2 = 2 * (lane & 3);
    int boff[2][2];
    #pragma unroll
    for (int m = 0; m < 2; m++)
        #pragma unroll
        for (int rr = 0; rr < 2; rr++)
            boff[m][rr] = (warp * 32 + m * 16 + (lane >> 2) + rr * 8) * BPITCH + c2;

    const uint32_t SC2h = f2h2(QK_SCALE * LOG2E, QK_SCALE * LOG2E);
    const uint32_t NEGO = f2h2(-EXP_OFF, -EXP_OFF);

    uint32_t o[2][4][2];
    uint32_t rsum2[2][2];
    #pragma unroll
    for (int m = 0; m < 2; m++) {
        #pragma unroll
        for (int n = 0; n < 4; n++) { o[m][n][0] = 0u; o[m][n][1] = 0u; }
        rsum2[m][0] = 0u; rsum2[m][1] = 0u;
    }

    for (int t = 0; t < TPS; t++) {
        CPA_WAIT0();
        __syncthreads();
        if (t < TPS - 1) issue_tile(tBeg + t + 1, (t + 1) & 1);
        const int s = t & 1;

        // --- S = Q K^T (f16 accumulate) ---
        uint32_t S[2][8][2];
        #pragma unroll
        for (int m = 0; m < 2; m++)
            #pragma unroll
            for (int n = 0; n < 8; n++) { S[m][n][0] = 0u; S[m][n][1] = 0u; }
        {
            const int brow = (lane & 7) + ((lane >> 4) & 1) * 8;
            const int bcol = ((lane >> 3) & 1) * 8;
            #pragma unroll
            for (int np = 0; np < 4; np++) {
                #pragma unroll
                for (int ks = 0; ks < 2; ks++) {
                    uint32_t kf[4];
                    uint32_t a = smem_u32(&Ks[s][(np * 16 + brow) * QPAD + ks * 16 + bcol]);
                    ldmx4(kf[0], kf[1], kf[2], kf[3], a);
                    #pragma unroll
                    for (int m = 0; m < 2; m++) {
                        mma16816h(S[m][2 * np],     qa[m][ks], kf[0], kf[1]);
                        mma16816h(S[m][2 * np + 1], qa[m][ks], kf[2], kf[3]);
                    }
                }
            }
        }

        // --- in-place half2 epilogue: P = 2^(S*c + bias - OFF) ---
        const unsigned char* bbuf = Bs[s];
        #pragma unroll
        for (int n = 0; n < 8; n++) {
            #pragma unroll
            for (int m = 0; m < 2; m++) {
                const unsigned short h0 = *(const unsigned short*)(bbuf + boff[m][0] + n * 8);
                const unsigned short h1 = *(const unsigned short*)(bbuf + boff[m][1] + n * 8);
                uint32_t b0, b1;
                asm("cvt.rn.f16x2.e4m3x2 %0, %1;" : "=r"(b0) : "h"(h0));
                asm("cvt.rn.f16x2.e4m3x2 %0, %1;" : "=r"(b1) : "h"(h1));
                b0 = hadd2u(b0, NEGO);
                b1 = hadd2u(b1, NEGO);
                S[m][n][0] = hex2u(hfma2u(S[m][n][0], SC2h, b0));
                S[m][n][1] = hex2u(hfma2u(S[m][n][1], SC2h, b1));
                rsum2[m][0] = hadd2u(rsum2[m][0], S[m][n][0]);
                rsum2[m][1] = hadd2u(rsum2[m][1], S[m][n][1]);
            }
        }

        // --- O += P @ V (f16 accumulate); S regs are the A-fragments ---
        {
            const int vrow = (lane & 7) + ((lane >> 3) & 1) * 8;
            const int vcol = ((lane >> 4) & 1) * 8;
            #pragma unroll
            for (int k2 = 0; k2 < 4; k2++) {
                #pragma unroll
                for (int dp = 0; dp < 2; dp++) {
                    uint32_t vf[4];
                    uint32_t a = smem_u32(&Vs[s][(k2 * 16 + vrow) * QPAD + dp * 16 + vcol]);
                    ldmx4t(vf[0], vf[1], vf[2], vf[3], a);
                    #pragma unroll
                    for (int m = 0; m < 2; m++) {
                        mma16816h(o[m][2 * dp],     &S[m][2 * k2][0], vf[0], vf[1]);
                        mma16816h(o[m][2 * dp + 1], &S[m][2 * k2][0], vf[2], vf[3]);
                    }
                }
            }
        }
    }

    // partial row sums -> gmem
    #pragma unroll
    for (int m = 0; m < 2; m++)
        #pragma unroll
        for (int rr = 0; rr < 2; rr++) {
            float2 f = h2f2(rsum2[m][rr]);
            float sv = f.x + f.y;
            sv += __shfl_xor_sync(0xFFFFFFFF, sv, 1);
            sv += __shfl_xor_sync(0xFFFFFFFF, sv, 2);
            if ((lane & 3) == 0) {
                const int grow = rowBase + warp * 32 + m * 16 + (lane >> 2) + rr * 8;
                g_rsP[(size_t)z * (BB * NH * HWP) + (size_t)(b * NH + h) * HWP + grow] = sv;
            }
        }

    // partial O (unnormalized, f16) -> gmem
    #pragma unroll
    for (int m = 0; m < 2; m++)
        #pragma unroll
        for (int rr = 0; rr < 2; rr++) {
            const int grow = rowBase + warp * 32 + m * 16 + (lane >> 2) + rr * 8;
            __half* od = g_Oph + (size_t)z * (BB * HWP * DM) + (size_t)(b * HWP + grow) * DM + h * DK;
            #pragma unroll
            for (int n = 0; n < 4; n++)
                *(uint32_t*)(od + n * 8 + c2) = o[m][n][rr];
        }
}

// ---------------------------------------------------------------------------
// Kernel 2b: combine KV-split partials: O = (o0+o1) / (r0+r1).
// ---------------------------------------------------------------------------
__global__ __launch_bounds__(256) void comb_kernel()
{
    const int idx = blockIdx.x * 256 + threadIdx.x;
    const int d    = (idx * 2) & (DM - 1);
    const int pidx = (idx * 2) >> 8;
    const int bb   = pidx / HWP;
    const int p    = pidx - bb * HWP;
    const int hh   = d >> 5;
    const size_t rsi = (size_t)(bb * NH + hh) * HWP + p;
    const float r = g_rsP[rsi] + g_rsP[(size_t)(BB * NH * HWP) + rsi];
    const float inv = __fdividef(1.0f, r);
    const uint32_t o0 = ((const uint32_t*)g_Oph)[idx];
    const uint32_t o1 = ((const uint32_t*)g_Oph)[idx + (BB * HWP * DM) / 2];
    float2 f0 = h2f2(o0), f1 = h2f2(o1);
    ((uint32_t*)g_Oh)[idx] = f2h2((f0.x + f1.x) * inv, (f0.y + f1.y) * inv);
}

// ---------------------------------------------------------------------------
// Kernel 3: HMMA output projection + residual, cp.async double-buffered.
// ---------------------------------------------------------------------------
__global__ __launch_bounds__(256) void outproj_mma_kernel(
    const float* __restrict__ x, const float* __restrict__ bo,
    const float* __restrict__ gamma_p, float* __restrict__ out)
{
    __shared__ __align__(16) __half ws2[2][64 * QPAD];    // 2 x 5120B
    __shared__ __align__(16) __half os2[2][128 * QPAD];   // 2 x 10240B

    const int tid  = threadIdx.x;
    const int warp = tid >> 5;
    const int lane = tid & 31;

    const int gp    = blockIdx.x * 128;
    const int b     = gp / HWP;
    const int pb    = gp - b * HWP;
    const int cBase = blockIdx.y * 64;
    const float gamma = *gamma_p;

    const uint32_t wsA = smem_u32(ws2);
    const uint32_t osA = smem_u32(os2);

    auto load_chunk = [&](int s, int k0) {
        const char* wb = (const char*)g_Woh + ((size_t)cBase * DM + k0) * 2;
        {
            const int i = tid;
            const int r = i >> 2, q = i & 3;
            CPA16(wsA + s * 5120 + r * 80 + q * 16, wb + (size_t)r * (DM * 2) + q * 16);
        }
        const char* ob = (const char*)g_Oh + ((size_t)(b * HWP + pb) * DM + k0) * 2;
        #pragma unroll
        for (int i = tid; i < 512; i += 256) {
            const int r = i >> 2, q = i & 3;
            CPA16(osA + s * 10240 + r * 80 + q * 16, ob + (size_t)r * (DM * 2) + q * 16);
        }
        CPA_COMMIT();
    };

    const int cw = warp & 1;
    const int pw = warp >> 1;

    float acc[2][4][4] = {};

    load_chunk(0, 0);

    for (int c = 0; c < 8; c++) {
        CPA_WAIT0();
        __syncthreads();
        if (c < 7) load_chunk((c + 1) & 1, (c + 1) * 32);
        const int s = c & 1;

        const int arow = (lane & 7) + ((lane >> 3) & 1) * 8;
        const int acol = (lane >> 4) * 8;
        const int brow = (lane & 7) + ((lane >> 4) & 1) * 8;
        const int bcol = ((lane >> 3) & 1) * 8;

        #pragma unroll
        for (int ks = 0; ks < 2; ks++) {
            uint32_t af[2][4];
            #pragma unroll
            for (int mt = 0; mt < 2; mt++) {
                uint32_t a = smem_u32(&ws2[s][(cw * 32 + mt * 16 + arow) * QPAD + ks * 16 + acol]);
                ldmx4(af[mt][0], af[mt][1], af[mt][2], af[mt][3], a);
            }
            #pragma unroll
            for (int nt = 0; nt < 2; nt++) {
                uint32_t bf[4];
                uint32_t a = smem_u32(&os2[s][(pw * 32 + nt * 16 + brow) * QPAD + ks * 16 + bcol]);
                ldmx4(bf[0], bf[1], bf[2], bf[3], a);
                #pragma unroll
                for (int mt = 0; mt < 2; mt++) {
                    mma16816f(acc[mt][2 * nt],     af[mt], bf);
                    mma16816f(acc[mt][2 * nt + 1], af[mt], bf + 2);
                }
            }
        }
    }

    const int c2 = 2 * (lane & 3);
    #pragma unroll
    for (int mt = 0; mt < 2; mt++) {
        #pragma unroll
        for (int rr = 0; rr < 2; rr++) {
            const int c = cBase + cw * 32 + mt * 16 + (lane >> 2) + rr * 8;
            const float bias = bo[c];
            #pragma unroll
            for (int n = 0; n < 4; n++) {
                const int p = pb + pw * 32 + n * 8 + c2;
                const size_t idx = (size_t)b * CC * HWP + (size_t)c * HWP + p;
                float2 xv = *(const float2*)(x + idx);
                float2 r;
                r.x = xv.x + gamma * acc[mt][n][rr * 2 + 0] + bias;
                r.y = xv.y + gamma * acc[mt][n][rr * 2 + 1] + bias;
                *(float2*)(out + idx) = r;
            }
        }
    }
}

// ---------------------------------------------------------------------------
extern "C" void kernel_launch(void* const* d_in, const int* in_sizes, int n_in,
                              void* d_out, int out_size)
{
    (void)in_sizes; (void)n_in; (void)out_size;
    const float* x   = (const float*)d_in[0];
    const float* Wq  = (const float*)d_in[1];
    const float* bq  = (const float*)d_in[2];
    const float* Wk  = (const float*)d_in[3];
    const float* bk  = (const float*)d_in[4];
    const float* Wv  = (const float*)d_in[5];
    const float* bv  = (const float*)d_in[6];
    const float* Wo  = (const float*)d_in[7];
    const float* bo  = (const float*)d_in[8];
    const float* lam = (const float*)d_in[9];
    const float* gam = (const float*)d_in[10];
    float* out = (float*)d_out;

    dtab_kernel<<<36, 256>>>(lam);
    bias_fill_kernel<<<(HWP * HWP / 4) / 256, 256>>>();
    convw_kernel<<<512, 256>>>(Wq, Wk, Wv, Wo);
    xt_kernel<<<dim3(HWP / 64, CC / 64, BB), 256>>>(x);

    qkv_mma_kernel<<<dim3(BB * HWP / 64, DM / 64), 256>>>(bq, bk, bv);

    attn_mma_kernel<<<dim3(HWP / 128, BB * NH, NSPLIT), 128>>>();
    comb_kernel<<<(BB * HWP * DM / 2) / 256, 256>>>();

    outproj_mma_kernel<<<dim3(BB * HWP / 128, CC / 64), 256>>>(x, bo, gam, out);
}

// round 11
// speedup vs baseline: 6.6455x; 1.0107x over previous
#include <cuda_runtime.h>
#include <cuda_fp16.h>
#include <cstdint>

#define BB 2
#define CC 256
#define HH 48
#define WW 48
#define HWP 2304
#define DM 256
#define NH 8
#define DK 32
#define QK_SCALE 0.17677669529663689f   // 1/sqrt(32)
#define LOG2E 1.4426950408889634f
#define EXP_OFF 7.0f                     // p scaled by 2^-7; cancels in softmax
#define QPAD 40                          // f16 pitch = 80B (16B multiple)
#define WPAD 40
#define BPITCH 80                        // bias tile pitch bytes (16B multiple for cp.async)
#define NSPLIT 2
#define NTILE (HWP / 64)                 // 36
#define TPS (NTILE / NSPLIT)             // 18 tiles per split

// ---------------- scratch (allocation-free) ----------------
__device__ __half g_Qh[BB * HWP * DM];
__device__ __half g_Kh[BB * HWP * DM];
__device__ __half g_Vh[BB * HWP * DM];
__device__ __half g_Oph[NSPLIT * BB * HWP * DM];   // partial attention out
__device__ float  g_rsP[NSPLIT * BB * NH * HWP];   // partial row sums
__device__ __half g_Oh[BB * HWP * DM];             // combined attention out
__device__ __half g_xh[BB * HWP * CC];             // x transposed (b,p,c)
__device__ __half g_Wqh[DM * CC];
__device__ __half g_Wkh[DM * CC];
__device__ __half g_Wvh[DM * CC];
__device__ __half g_Woh[CC * DM];
__device__ unsigned char g_dtab[95 * 95];          // e4m3(lam*exp(-d)*log2e) per (dy,dx)
__device__ unsigned char g_biasF8[HWP * HWP];      // expanded bias matrix

// ---------------- helpers ----------------
__device__ __forceinline__ uint32_t smem_u32(const void* p) {
    uint32_t a;
    asm("{ .reg .u64 t; cvta.to.shared.u64 t, %1; cvt.u32.u64 %0, t; }" : "=r"(a) : "l"(p));
    return a;
}
__device__ __forceinline__ void ldmx4(uint32_t& r0, uint32_t& r1, uint32_t& r2, uint32_t& r3, uint32_t a) {
    asm volatile("ldmatrix.sync.aligned.m8n8.x4.shared.b16 {%0,%1,%2,%3}, [%4];"
                 : "=r"(r0), "=r"(r1), "=r"(r2), "=r"(r3) : "r"(a));
}
__device__ __forceinline__ void ldmx4t(uint32_t& r0, uint32_t& r1, uint32_t& r2, uint32_t& r3, uint32_t a) {
    asm volatile("ldmatrix.sync.aligned.m8n8.x4.trans.shared.b16 {%0,%1,%2,%3}, [%4];"
                 : "=r"(r0), "=r"(r1), "=r"(r2), "=r"(r3) : "r"(a));
}
__device__ __forceinline__ void mma16816f(float* c, const uint32_t* a, const uint32_t* b) {
    asm volatile("mma.sync.aligned.m16n8k16.row.col.f32.f16.f16.f32 "
                 "{%0,%1,%2,%3},{%4,%5,%6,%7},{%8,%9},{%0,%1,%2,%3};"
                 : "+f"(c[0]), "+f"(c[1]), "+f"(c[2]), "+f"(c[3])
                 : "r"(a[0]), "r"(a[1]), "r"(a[2]), "r"(a[3]), "r"(b[0]), "r"(b[1]));
}
__device__ __forceinline__ void mma16816h(uint32_t* d, const uint32_t* a, uint32_t b0, uint32_t b1) {
    asm volatile("mma.sync.aligned.m16n8k16.row.col.f16.f16.f16.f16 "
                 "{%0,%1},{%2,%3,%4,%5},{%6,%7},{%0,%1};"
                 : "+r"(d[0]), "+r"(d[1])
                 : "r"(a[0]), "r"(a[1]), "r"(a[2]), "r"(a[3]), "r"(b0), "r"(b1));
}
__device__ __forceinline__ uint32_t f2h2(float lo, float hi) {
    __half2 h = __floats2half2_rn(lo, hi);
    return *(uint32_t*)&h;
}
__device__ __forceinline__ uint32_t hfma2u(uint32_t a, uint32_t b, uint32_t c) {
    uint32_t d;
    asm("fma.rn.f16x2 %0, %1, %2, %3;" : "=r"(d) : "r"(a), "r"(b), "r"(c));
    return d;
}
__device__ __forceinline__ uint32_t hadd2u(uint32_t a, uint32_t b) {
    uint32_t d;
    asm("add.rn.f16x2 %0, %1, %2;" : "=r"(d) : "r"(a), "r"(b));
    return d;
}
__device__ __forceinline__ uint32_t hex2u(uint32_t a) {
    uint32_t d;
    asm("ex2.approx.f16x2 %0, %1;" : "=r"(d) : "r"(a));
    return d;
}
__device__ __forceinline__ float2 h2f2(uint32_t u) {
    __half2 h = *(__half2*)&u;
    return __half22float2(h);
}
#define CPA16(dst, src) asm volatile("cp.async.cg.shared.global [%0], [%1], 16;" :: "r"(dst), "l"(src))
#define CPA_COMMIT()    asm volatile("cp.async.commit_group;")
#define CPA_WAIT0()     asm volatile("cp.async.wait_group 0;")

// ---------------------------------------------------------------------------
// Prep A (merged): blocks [0,512): convert W fp32->f16; blocks [512,548): dtab.
// ---------------------------------------------------------------------------
__global__ __launch_bounds__(256) void prep_kernel(
    const float* __restrict__ lam_p,
    const float* __restrict__ Wq, const float* __restrict__ Wk,
    const float* __restrict__ Wv, const float* __restrict__ Wo)
{
    const int bx = blockIdx.x;
    if (bx < 512) {
        const int idx = bx * 256 + threadIdx.x;
        const int mat = idx >> 15;
        const int off = idx & 32767;
        const float* s = (mat == 0) ? Wq : ((mat == 1) ? Wk : ((mat == 2) ? Wv : Wo));
        uint32_t* d = (uint32_t*)((mat == 0) ? g_Wqh : ((mat == 1) ? g_Wkh : ((mat == 2) ? g_Wvh : g_Woh)));
        d[off] = f2h2(s[off * 2], s[off * 2 + 1]);
    } else {
        const int idx = (bx - 512) * 256 + threadIdx.x;
        if (idx >= 95 * 95) return;
        const float lam2 = (*lam_p) * LOG2E;
        const int dy = idx / 95 - 47;
        const int dx = idx % 95 - 47;
        const float t = lam2 * __expf(-sqrtf((float)(dy * dy + dx * dx)));
        unsigned short u;
        asm("cvt.rn.satfinite.e4m3x2.f32 %0, %1, %2;" : "=h"(u) : "f"(t), "f"(t));
        g_dtab[idx] = (unsigned char)(u & 0xFF);
    }
}

// ---------------------------------------------------------------------------
// Prep B: expand bias matrix by table lookup (bandwidth-bound gather).
// ---------------------------------------------------------------------------
__global__ __launch_bounds__(256) void bias_fill_kernel()
{
    const int idx = blockIdx.x * 256 + threadIdx.x;   // HWP*HWP/4
    const int i  = idx / (HWP / 4);
    const int j0 = (idx - i * (HWP / 4)) * 4;
    const int yi = i / WW, xi = i - yi * WW;
    uint32_t out = 0;
    #pragma unroll
    for (int u = 0; u < 4; u++) {
        const int j  = j0 + u;
        const int yj = j / WW;
        const int xj = j - yj * WW;
        const int ti = (yi - yj + 47) * 95 + (xi - xj + 47);
        out |= (uint32_t)g_dtab[ti] << (u * 8);
    }
    ((uint32_t*)g_biasF8)[idx] = out;
}

// ---------------------------------------------------------------------------
// Prep C: transpose+convert x (b,c,p) fp32 -> g_xh (b,p,c) f16 (vectorized).
// ---------------------------------------------------------------------------
__global__ __launch_bounds__(256) void xt_kernel(const float* __restrict__ x)
{
    __shared__ float ts[64][65];
    const int b  = blockIdx.z;
    const int pB = blockIdx.x * 64;
    const int cB = blockIdx.y * 64;
    #pragma unroll
    for (int i = threadIdx.x; i < 1024; i += 256) {
        const int c  = i >> 4;
        const int pq = (i & 15) * 4;
        const float4 v = *(const float4*)&x[((size_t)b * CC + cB + c) * HWP + pB + pq];
        ts[c][pq + 0] = v.x;
        ts[c][pq + 1] = v.y;
        ts[c][pq + 2] = v.z;
        ts[c][pq + 3] = v.w;
    }
    __syncthreads();
    #pragma unroll
    for (int i = threadIdx.x; i < 1024; i += 256) {
        const int p  = i >> 4;
        const int cq = (i & 15) * 4;
        uint2 o;
        o.x = f2h2(ts[cq + 0][p], ts[cq + 1][p]);
        o.y = f2h2(ts[cq + 2][p], ts[cq + 3][p]);
        *(uint2*)(g_xh + ((size_t)(b * HWP + pB + p) * CC + cB + cq)) = o;
    }
}

// ---------------------------------------------------------------------------
// Kernel 1: HMMA fused QKV + pe + bias, 2-stage cp.async pipeline.
// CTA 256 thr: M=64 pixels x N=64 dims, all 3 matrices. Grid (72, 4).
// ---------------------------------------------------------------------------
__global__ __launch_bounds__(256) void qkv_mma_kernel(
    const float* __restrict__ bq, const float* __restrict__ bk, const float* __restrict__ bv)
{
    __shared__ __align__(16) __half As[2][64 * QPAD];       // 2 x 5120B
    __shared__ __align__(16) __half Ws[2][3][64 * WPAD];    // 2 x 15360B

    const int tid  = threadIdx.x;
    const int warp = tid >> 5;
    const int lane = tid & 31;

    const int gp    = blockIdx.x * 64;
    const int b     = gp / HWP;
    const int pb    = gp - b * HWP;
    const int dBase = blockIdx.y * 64;
    const bool use_y = (dBase >= 128);

    const uint32_t asA = smem_u32(As);
    const uint32_t wsA = smem_u32(Ws);

    const __half* gW[3] = { g_Wqh, g_Wkh, g_Wvh };

    auto load_chunk = [&](int s, int c0) {
        const char* ab = (const char*)g_xh + ((size_t)(b * HWP + pb) * CC + c0) * 2;
        {
            const int i = tid;
            const int r = i >> 2, q = i & 3;
            CPA16(asA + s * 5120 + r * 80 + q * 16, ab + (size_t)r * (CC * 2) + q * 16);
        }
        #pragma unroll
        for (int i = tid; i < 768; i += 256) {
            const int mat = i / 256;
            const int rem = i - mat * 256;
            const int r = rem >> 2, q = rem & 3;
            const char* wb = (const char*)gW[mat] + ((size_t)(dBase + r) * CC + c0) * 2;
            CPA16(wsA + s * 15360 + mat * 5120 + r * 80 + q * 16, wb + q * 16);
        }
        CPA_COMMIT();
    };

    const int mw = warp >> 2;      // rows mw*32
    const int nw = warp & 3;       // dims nw*16

    float acc[3][2][2][4] = {};

    load_chunk(0, 0);

    for (int c = 0; c < 8; c++) {
        CPA_WAIT0();
        __syncthreads();
        if (c < 7) load_chunk((c + 1) & 1, (c + 1) * 32);

        const int s = c & 1;
        const __half* Ab = As[s];

        const int arow = (lane & 7) + ((lane >> 3) & 1) * 8;
        const int acol = (lane >> 4) * 8;
        const int brow = (lane & 7) + ((lane >> 4) & 1) * 8;
        const int bcol = ((lane >> 3) & 1) * 8;

        #pragma unroll
        for (int ks = 0; ks < 2; ks++) {
            uint32_t af[2][4];
            #pragma unroll
            for (int mt = 0; mt < 2; mt++) {
                uint32_t a = smem_u32(Ab + (mw * 32 + mt * 16 + arow) * QPAD + ks * 16 + acol);
                ldmx4(af[mt][0], af[mt][1], af[mt][2], af[mt][3], a);
            }
            #pragma unroll
            for (int mat = 0; mat < 3; mat++) {
                uint32_t bf[4];
                uint32_t a = smem_u32(&Ws[s][mat][(nw * 16 + brow) * WPAD + ks * 16 + bcol]);
                ldmx4(bf[0], bf[1], bf[2], bf[3], a);
                #pragma unroll
                for (int mt = 0; mt < 2; mt++) {
                    mma16816f(acc[mat][mt][0], af[mt], bf);
                    mma16816f(acc[mat][mt][1], af[mt], bf + 2);
                }
            }
        }
    }

    // pe table (f16) in the now-free A staging region
    __syncthreads();
    __half* pes = (__half*)As;   // [coord 0..47][dloc 0..63]
    for (int i = tid; i < 48 * 64; i += 256) {
        const int coord = i >> 6;
        const int dloc  = i & 63;
        const int dl    = (dBase + dloc) - (use_y ? 128 : 0);
        const float freq = __expf(-(float)(dl >> 1) * 0.14391156642875743f);
        const float arg  = (float)coord * freq;
        pes[i] = __float2half((dl & 1) ? __cosf(arg) : __sinf(arg));
    }
    __syncthreads();

    const int c2 = 2 * (lane & 3);
    #pragma unroll
    for (int mt = 0; mt < 2; mt++) {
        #pragma unroll
        for (int rr = 0; rr < 2; rr++) {
            const int ploc = mw * 32 + mt * 16 + (lane >> 2) + rr * 8;
            const int p    = pb + ploc;
            const int coord = use_y ? (p / WW) : (p % WW);
            const size_t rowIdx = ((size_t)b * HWP + p) * DM + dBase;
            #pragma unroll
            for (int nt = 0; nt < 2; nt++) {
                const int dloc = nw * 16 + nt * 8 + c2;
                const int d    = dBase + dloc;
                const float pe0 = __half2float(pes[coord * 64 + dloc]);
                const float pe1 = __half2float(pes[coord * 64 + dloc + 1]);
                const float q0 = acc[0][mt][nt][rr * 2 + 0] + bq[d]     + pe0;
                const float q1 = acc[0][mt][nt][rr * 2 + 1] + bq[d + 1] + pe1;
                const float k0 = acc[1][mt][nt][rr * 2 + 0] + bk[d]     + pe0;
                const float k1 = acc[1][mt][nt][rr * 2 + 1] + bk[d + 1] + pe1;
                const float v0 = acc[2][mt][nt][rr * 2 + 0] + bv[d];
                const float v1 = acc[2][mt][nt][rr * 2 + 1] + bv[d + 1];
                *(uint32_t*)(g_Qh + rowIdx + dloc) = f2h2(q0, q1);
                *(uint32_t*)(g_Kh + rowIdx + dloc) = f2h2(k0, k1);
                *(uint32_t*)(g_Vh + rowIdx + dloc) = f2h2(v0, v1);
            }
        }
    }
}

// ---------------------------------------------------------------------------
// Kernel 2: f16 HMMA flash attention, KV-split across z (unchanged from R10).
// ---------------------------------------------------------------------------
__global__ __launch_bounds__(128, 4) void attn_mma_kernel()
{
    __shared__ __align__(16) __half Qs[128 * QPAD];
    __shared__ __align__(16) __half Ks[2][64 * QPAD];
    __shared__ __align__(16) __half Vs[2][64 * QPAD];
    __shared__ __align__(16) unsigned char Bs[2][128 * BPITCH];

    const int tid  = threadIdx.x;
    const int warp = tid >> 5;
    const int lane = tid & 31;
    const int b    = blockIdx.y >> 3;
    const int h    = blockIdx.y & 7;
    const int rowBase = blockIdx.x * 128;
    const int z    = blockIdx.z;
    const int tBeg = z * TPS;

    const uint32_t ksA = smem_u32(Ks);
    const uint32_t vsA = smem_u32(Vs);
    const uint32_t bsA = smem_u32(Bs);

    auto issue_tile = [&](int t, int s) {
        const int jt = t * 64;
        const char* kb = (const char*)g_Kh + ((size_t)(b * HWP + jt) * DM + h * DK) * 2;
        const char* vb = (const char*)g_Vh + ((size_t)(b * HWP + jt) * DM + h * DK) * 2;
        #pragma unroll
        for (int i = tid; i < 256; i += 128) {
            const int r = i >> 2, q = i & 3;
            CPA16(ksA + s * 5120 + r * 80 + q * 16, kb + (size_t)r * (DM * 2) + q * 16);
            CPA16(vsA + s * 5120 + r * 80 + q * 16, vb + (size_t)r * (DM * 2) + q * 16);
        }
        const unsigned char* bb = g_biasF8 + (size_t)rowBase * HWP + jt;
        #pragma unroll
        for (int i = tid; i < 512; i += 128) {
            const int r = i >> 2, q = i & 3;
            CPA16(bsA + s * 10240 + r * BPITCH + q * 16, bb + (size_t)r * HWP + q * 16);
        }
        CPA_COMMIT();
    };

    {
        const __half* qsrc = g_Qh + (size_t)(b * HWP + rowBase) * DM + h * DK;
        #pragma unroll
        for (int i = tid; i < 512; i += 128) {
            const int r = i >> 2, q = i & 3;
            *(uint4*)(Qs + r * QPAD + q * 8) = *(const uint4*)(qsrc + (size_t)r * DM + q * 8);
        }
    }
    issue_tile(tBeg, 0);
    __syncthreads();

    uint32_t qa[2][2][4];
    {
        const int arow = (lane & 7) + ((lane >> 3) & 1) * 8;
        const int acol = (lane >> 4) * 8;
        #pragma unroll
        for (int m = 0; m < 2; m++)
            #pragma unroll
            for (int ks = 0; ks < 2; ks++) {
                uint32_t a = smem_u32(Qs + (warp * 32 + m * 16 + arow) * QPAD + ks * 16 + acol);
                ldmx4(qa[m][ks][0], qa[m][ks][1], qa[m][ks][2], qa[m][ks][3], a);
            }
    }

    const int c2 = 2 * (lane & 3);
    int boff[2][2];
    #pragma unroll
    for (int m = 0; m < 2; m++)
        #pragma unroll
        for (int rr = 0; rr < 2; rr++)
            boff[m][rr] = (warp * 32 + m * 16 + (lane >> 2) + rr * 8) * BPITCH + c2;

    const uint32_t SC2h = f2h2(QK_SCALE * LOG2E, QK_SCALE * LOG2E);
    const uint32_t NEGO = f2h2(-EXP_OFF, -EXP_OFF);

    uint32_t o[2][4][2];
    uint32_t rsum2[2][2];
    #pragma unroll
    for (int m = 0; m < 2; m++) {
        #pragma unroll
        for (int n = 0; n < 4; n++) { o[m][n][0] = 0u; o[m][n][1] = 0u; }
        rsum2[m][0] = 0u; rsum2[m][1] = 0u;
    }

    for (int t = 0; t < TPS; t++) {
        CPA_WAIT0();
        __syncthreads();
        if (t < TPS - 1) issue_tile(tBeg + t + 1, (t + 1) & 1);
        const int s = t & 1;

        uint32_t S[2][8][2];
        #pragma unroll
        for (int m = 0; m < 2; m++)
            #pragma unroll
            for (int n = 0; n < 8; n++) { S[m][n][0] = 0u; S[m][n][1] = 0u; }
        {
            const int brow = (lane & 7) + ((lane >> 4) & 1) * 8;
            const int bcol = ((lane >> 3) & 1) * 8;
            #pragma unroll
            for (int np = 0; np < 4; np++) {
                #pragma unroll
                for (int ks = 0; ks < 2; ks++) {
                    uint32_t kf[4];
                    uint32_t a = smem_u32(&Ks[s][(np * 16 + brow) * QPAD + ks * 16 + bcol]);
                    ldmx4(kf[0], kf[1], kf[2], kf[3], a);
                    #pragma unroll
                    for (int m = 0; m < 2; m++) {
                        mma16816h(S[m][2 * np],     qa[m][ks], kf[0], kf[1]);
                        mma16816h(S[m][2 * np + 1], qa[m][ks], kf[2], kf[3]);
                    }
                }
            }
        }

        const unsigned char* bbuf = Bs[s];
        #pragma unroll
        for (int n = 0; n < 8; n++) {
            #pragma unroll
            for (int m = 0; m < 2; m++) {
                const unsigned short h0 = *(const unsigned short*)(bbuf + boff[m][0] + n * 8);
                const unsigned short h1 = *(const unsigned short*)(bbuf + boff[m][1] + n * 8);
                uint32_t b0, b1;
                asm("cvt.rn.f16x2.e4m3x2 %0, %1;" : "=r"(b0) : "h"(h0));
                asm("cvt.rn.f16x2.e4m3x2 %0, %1;" : "=r"(b1) : "h"(h1));
                b0 = hadd2u(b0, NEGO);
                b1 = hadd2u(b1, NEGO);
                S[m][n][0] = hex2u(hfma2u(S[m][n][0], SC2h, b0));
                S[m][n][1] = hex2u(hfma2u(S[m][n][1], SC2h, b1));
                rsum2[m][0] = hadd2u(rsum2[m][0], S[m][n][0]);
                rsum2[m][1] = hadd2u(rsum2[m][1], S[m][n][1]);
            }
        }

        {
            const int vrow = (lane & 7) + ((lane >> 3) & 1) * 8;
            const int vcol = ((lane >> 4) & 1) * 8;
            #pragma unroll
            for (int k2 = 0; k2 < 4; k2++) {
                #pragma unroll
                for (int dp = 0; dp < 2; dp++) {
                    uint32_t vf[4];
                    uint32_t a = smem_u32(&Vs[s][(k2 * 16 + vrow) * QPAD + dp * 16 + vcol]);
                    ldmx4t(vf[0], vf[1], vf[2], vf[3], a);
                    #pragma unroll
                    for (int m = 0; m < 2; m++) {
                        mma16816h(o[m][2 * dp],     &S[m][2 * k2][0], vf[0], vf[1]);
                        mma16816h(o[m][2 * dp + 1], &S[m][2 * k2][0], vf[2], vf[3]);
                    }
                }
            }
        }
    }

    #pragma unroll
    for (int m = 0; m < 2; m++)
        #pragma unroll
        for (int rr = 0; rr < 2; rr++) {
            float2 f = h2f2(rsum2[m][rr]);
            float sv = f.x + f.y;
            sv += __shfl_xor_sync(0xFFFFFFFF, sv, 1);
            sv += __shfl_xor_sync(0xFFFFFFFF, sv, 2);
            if ((lane & 3) == 0) {
                const int grow = rowBase + warp * 32 + m * 16 + (lane >> 2) + rr * 8;
                g_rsP[(size_t)z * (BB * NH * HWP) + (size_t)(b * NH + h) * HWP + grow] = sv;
            }
        }

    #pragma unroll
    for (int m = 0; m < 2; m++)
        #pragma unroll
        for (int rr = 0; rr < 2; rr++) {
            const int grow = rowBase + warp * 32 + m * 16 + (lane >> 2) + rr * 8;
            __half* od = g_Oph + (size_t)z * (BB * HWP * DM) + (size_t)(b * HWP + grow) * DM + h * DK;
            #pragma unroll
            for (int n = 0; n < 4; n++)
                *(uint32_t*)(od + n * 8 + c2) = o[m][n][rr];
        }
}

// ---------------------------------------------------------------------------
// Kernel 2b: combine KV-split partials: O = (o0+o1) / (r0+r1).
// ---------------------------------------------------------------------------
__global__ __launch_bounds__(256) void comb_kernel()
{
    const int idx = blockIdx.x * 256 + threadIdx.x;
    const int d    = (idx * 2) & (DM - 1);
    const int pidx = (idx * 2) >> 8;
    const int bb   = pidx / HWP;
    const int p    = pidx - bb * HWP;
    const int hh   = d >> 5;
    const size_t rsi = (size_t)(bb * NH + hh) * HWP + p;
    const float r = g_rsP[rsi] + g_rsP[(size_t)(BB * NH * HWP) + rsi];
    const float inv = __fdividef(1.0f, r);
    const uint32_t o0 = ((const uint32_t*)g_Oph)[idx];
    const uint32_t o1 = ((const uint32_t*)g_Oph)[idx + (BB * HWP * DM) / 2];
    float2 f0 = h2f2(o0), f1 = h2f2(o1);
    ((uint32_t*)g_Oh)[idx] = f2h2((f0.x + f1.x) * inv, (f0.y + f1.y) * inv);
}

// ---------------------------------------------------------------------------
// Kernel 3: HMMA output projection + residual, 64x64 tiles, 2-stage cp.async.
// CTA 256 thr: M=64 c x N=64 p. Grid (72, 4).
// ---------------------------------------------------------------------------
__global__ __launch_bounds__(256) void outproj_mma_kernel(
    const float* __restrict__ x, const float* __restrict__ bo,
    const float* __restrict__ gamma_p, float* __restrict__ out)
{
    __shared__ __align__(16) __half ws2[2][64 * QPAD];    // 2 x 5120B
    __shared__ __align__(16) __half os2[2][64 * QPAD];    // 2 x 5120B

    const int tid  = threadIdx.x;
    const int warp = tid >> 5;
    const int lane = tid & 31;

    const int gp    = blockIdx.x * 64;
    const int b     = gp / HWP;
    const int pb    = gp - b * HWP;
    const int cBase = blockIdx.y * 64;
    const float gamma = *gamma_p;

    const uint32_t wsA = smem_u32(ws2);
    const uint32_t osA = smem_u32(os2);

    auto load_chunk = [&](int s, int k0) {
        const char* wb = (const char*)g_Woh + ((size_t)cBase * DM + k0) * 2;
        const char* ob = (const char*)g_Oh + ((size_t)(b * HWP + pb) * DM + k0) * 2;
        {
            const int i = tid;   // 256 chunks each
            const int r = i >> 2, q = i & 3;
            CPA16(wsA + s * 5120 + r * 80 + q * 16, wb + (size_t)r * (DM * 2) + q * 16);
            CPA16(osA + s * 5120 + r * 80 + q * 16, ob + (size_t)r * (DM * 2) + q * 16);
        }
        CPA_COMMIT();
    };

    const int cw = warp >> 2;    // c-group: rows cw*32
    const int pw = warp & 3;     // p-group: cols pw*16

    float acc[2][2][4] = {};     // [mt][nt(n8)][frag]

    load_chunk(0, 0);

    for (int c = 0; c < 8; c++) {
        CPA_WAIT0();
        __syncthreads();
        if (c < 7) load_chunk((c + 1) & 1, (c + 1) * 32);
        const int s = c & 1;

        const int arow = (lane & 7) + ((lane >> 3) & 1) * 8;
        const int acol = (lane >> 4) * 8;
        const int brow = (lane & 7) + ((lane >> 4) & 1) * 8;
        const int bcol = ((lane >> 3) & 1) * 8;

        #pragma unroll
        for (int ks = 0; ks < 2; ks++) {
            uint32_t af[2][4];
            #pragma unroll
            for (int mt = 0; mt < 2; mt++) {
                uint32_t a = smem_u32(&ws2[s][(cw * 32 + mt * 16 + arow) * QPAD + ks * 16 + acol]);
                ldmx4(af[mt][0], af[mt][1], af[mt][2], af[mt][3], a);
            }
            uint32_t bf[4];
            uint32_t a = smem_u32(&os2[s][(pw * 16 + brow) * QPAD + ks * 16 + bcol]);
            ldmx4(bf[0], bf[1], bf[2], bf[3], a);
            #pragma unroll
            for (int mt = 0; mt < 2; mt++) {
                mma16816f(acc[mt][0], af[mt], bf);
                mma16816f(acc[mt][1], af[mt], bf + 2);
            }
        }
    }

    const int c2 = 2 * (lane & 3);
    #pragma unroll
    for (int mt = 0; mt < 2; mt++) {
        #pragma unroll
        for (int rr = 0; rr < 2; rr++) {
            const int c = cBase + cw * 32 + mt * 16 + (lane >> 2) + rr * 8;
            const float bias = bo[c];
            #pragma unroll
            for (int nt = 0; nt < 2; nt++) {
                const int p = pb + pw * 16 + nt * 8 + c2;
                const size_t idx = (size_t)b * CC * HWP + (size_t)c * HWP + p;
                float2 xv = *(const float2*)(x + idx);
                float2 r;
                r.x = xv.x + gamma * acc[mt][nt][rr * 2 + 0] + bias;
                r.y = xv.y + gamma * acc[mt][nt][rr * 2 + 1] + bias;
                *(float2*)(out + idx) = r;
            }
        }
    }
}

// ---------------------------------------------------------------------------
extern "C" void kernel_launch(void* const* d_in, const int* in_sizes, int n_in,
                              void* d_out, int out_size)
{
    (void)in_sizes; (void)n_in; (void)out_size;
    const float* x   = (const float*)d_in[0];
    const float* Wq  = (const float*)d_in[1];
    const float* bq  = (const float*)d_in[2];
    const float* Wk  = (const float*)d_in[3];
    const float* bk  = (const float*)d_in[4];
    const float* Wv  = (const float*)d_in[5];
    const float* bv  = (const float*)d_in[6];
    const float* Wo  = (const float*)d_in[7];
    const float* bo  = (const float*)d_in[8];
    const float* lam = (const float*)d_in[9];
    const float* gam = (const float*)d_in[10];
    float* out = (float*)d_out;

    prep_kernel<<<548, 256>>>(lam, Wq, Wk, Wv, Wo);
    bias_fill_kernel<<<(HWP * HWP / 4) / 256, 256>>>();
    xt_kernel<<<dim3(HWP / 64, CC / 64, BB), 256>>>(x);

    qkv_mma_kernel<<<dim3(BB * HWP / 64, DM / 64), 256>>>(bq, bk, bv);

    attn_mma_kernel<<<dim3(HWP / 128, BB * NH, NSPLIT), 128>>>();
    comb_kernel<<<(BB * HWP * DM / 2) / 256, 256>>>();

    outproj_mma_kernel<<<dim3(BB * HWP / 64, CC / 64), 256>>>(x, bo, gam, out);
}